// round 2
// baseline (speedup 1.0000x reference)
#include <cuda_runtime.h>

#define NROWS 32768
#define BSZ   1024
#define AGN   32
#define IND   96
#define HDIM  64
#define NNHD  64
#define ATTD  32
#define NACTD 16
#define LDIM  16
#define DLAT  512

typedef unsigned long long u64;

// ---------------- scratch (device globals; no runtime allocation) ----------------
__device__ float g_z1[NROWS * NNHD];
__device__ float g_q[NROWS * NACTD];
__device__ float g_query[NROWS * ATTD];
__device__ float g_m1h[NROWS * NNHD];
__device__ float g_lat[BSZ * AGN * AGN * LDIM];   // [b][j][i][l]
__device__ float g_alpha[BSZ * AGN * AGN];        // [b][j][i]
__device__ float g_bn_a[NNHD];
__device__ float g_bn_c[NNHD];
__device__ float g_p1[128 * NNHD];                // BN partial sums
__device__ float g_p2[128 * NNHD];                // BN partial sumsq

// ---------------- packed f32x2 helpers ----------------
__device__ __forceinline__ u64 pk2(float lo, float hi) {
    u64 r; asm("mov.b64 %0, {%1, %2};" : "=l"(r) : "f"(lo), "f"(hi)); return r;
}
__device__ __forceinline__ void upk2(float& lo, float& hi, u64 v) {
    asm("mov.b64 {%0, %1}, %2;" : "=f"(lo), "=f"(hi) : "l"(v));
}
__device__ __forceinline__ u64 fma2_(u64 a, u64 b, u64 c) {
    u64 d; asm("fma.rn.f32x2 %0, %1, %2, %3;" : "=l"(d) : "l"(a), "l"(b), "l"(c)); return d;
}
__device__ __forceinline__ float red4(u64 a0, u64 a1, u64 a2, u64 a3) {
    float r0,r1,r2,r3,r4,r5,r6,r7;
    upk2(r0,r1,a0); upk2(r2,r3,a1); upk2(r4,r5,a2); upk2(r6,r7,a3);
    return ((r0+r1)+(r2+r3))+((r4+r5)+(r6+r7));
}

__device__ __forceinline__ float dot64p(const float* __restrict__ w, const u64 (&z)[32]) {
    const float4* w4 = reinterpret_cast<const float4*>(w);
    u64 a0=0ull, a1=0ull, a2=0ull, a3=0ull;
#pragma unroll
    for (int k = 0; k < 16; k++) {
        float4 u = __ldg(w4 + k);
        u64 w0 = pk2(u.x, u.y), w1 = pk2(u.z, u.w);
        if (k & 1) { a2 = fma2_(w0, z[2*k], a2); a3 = fma2_(w1, z[2*k+1], a3); }
        else       { a0 = fma2_(w0, z[2*k], a0); a1 = fma2_(w1, z[2*k+1], a1); }
    }
    return red4(a0,a1,a2,a3);
}

__device__ __forceinline__ float dot96p(const float* __restrict__ w, const u64 (&z)[48]) {
    const float4* w4 = reinterpret_cast<const float4*>(w);
    u64 a0=0ull, a1=0ull, a2=0ull, a3=0ull;
#pragma unroll
    for (int k = 0; k < 24; k++) {
        float4 u = __ldg(w4 + k);
        u64 w0 = pk2(u.x, u.y), w1 = pk2(u.z, u.w);
        if (k & 1) { a2 = fma2_(w0, z[2*k], a2); a3 = fma2_(w1, z[2*k+1], a3); }
        else       { a0 = fma2_(w0, z[2*k], a0); a1 = fma2_(w1, z[2*k+1], a1); }
    }
    return red4(a0,a1,a2,a3);
}

__device__ __forceinline__ float sigmoidf_(float x) { return 1.f / (1.f + expf(-x)); }

// ---------------- K1: fused trunk ----------------
__global__ void __launch_bounds__(128) k1_trunk(
    const float* __restrict__ inp, const float* __restrict__ h0,
    const float* __restrict__ fc1_w, const float* __restrict__ fc1_b,
    const float* __restrict__ wih, const float* __restrict__ whh,
    const float* __restrict__ bih, const float* __restrict__ bhh,
    const float* __restrict__ fc2_w, const float* __restrict__ fc2_b,
    const float* __restrict__ emb_w1, const float* __restrict__ emb_b1,
    const float* __restrict__ wq_w, const float* __restrict__ wq_b,
    const float* __restrict__ msg_w1, const float* __restrict__ msg_b1,
    float* __restrict__ h_out)
{
    extern __shared__ float sm1[];
    float* sX  = sm1;                 // x (post-relu), scalar, 128*65
    float* sH0 = sm1 + 128 * 65;      // h_in scalar
    float* sHn = sm1 + 2 * 128 * 65;  // new h scalar
    const int tid = threadIdx.x;
    const int row = blockIdx.x * 128 + tid;
    float* myX  = sX  + tid * 65;
    float* myH0 = sH0 + tid * 65;
    float* myHn = sHn + tid * 65;

    // input row packed
    u64 xinp[48];
    {
        const float4* ip = reinterpret_cast<const float4*>(inp + (size_t)row * IND);
#pragma unroll
        for (int k = 0; k < 24; k++) {
            float4 v = __ldg(ip + k);
            xinp[2*k] = pk2(v.x, v.y); xinp[2*k+1] = pk2(v.z, v.w);
        }
    }
    // h0 packed + scalar smem copy
    u64 hrp[32];
    {
        const float4* hp = reinterpret_cast<const float4*>(h0 + (size_t)row * HDIM);
#pragma unroll
        for (int k = 0; k < 16; k++) {
            float4 v = __ldg(hp + k);
            hrp[2*k] = pk2(v.x, v.y); hrp[2*k+1] = pk2(v.z, v.w);
            myH0[4*k] = v.x; myH0[4*k+1] = v.y; myH0[4*k+2] = v.z; myH0[4*k+3] = v.w;
        }
    }

    // fc1 + relu
    for (int o = 0; o < HDIM; o++) {
        float acc = __ldg(fc1_b + o) + dot96p(fc1_w + o * IND, xinp);
        myX[o] = fmaxf(acc, 0.f);
    }
    u64 xrp[32];
#pragma unroll
    for (int k = 0; k < 32; k++) xrp[k] = pk2(myX[2*k], myX[2*k+1]);

    // GRU
    for (int o = 0; o < HDIM; o++) {
        float ar = __ldg(bih + o) + __ldg(bhh + o)
                 + dot64p(wih + o * HDIM, xrp) + dot64p(whh + o * HDIM, hrp);
        float az = __ldg(bih + HDIM + o) + __ldg(bhh + HDIM + o)
                 + dot64p(wih + (HDIM + o) * HDIM, xrp) + dot64p(whh + (HDIM + o) * HDIM, hrp);
        float ai = __ldg(bih + 2 * HDIM + o) + dot64p(wih + (2 * HDIM + o) * HDIM, xrp);
        float ah = __ldg(bhh + 2 * HDIM + o) + dot64p(whh + (2 * HDIM + o) * HDIM, hrp);
        float r = sigmoidf_(ar);
        float z = sigmoidf_(az);
        float n = tanhf(ai + r * ah);
        myHn[o] = (1.f - z) * n + z * myH0[o];
    }
#pragma unroll
    for (int k = 0; k < 32; k++) hrp[k] = pk2(myHn[2*k], myHn[2*k+1]);

    // h out
    {
        float4* hop = reinterpret_cast<float4*>(h_out + (size_t)row * HDIM);
#pragma unroll
        for (int k = 0; k < 16; k++)
            hop[k] = make_float4(myHn[4*k], myHn[4*k+1], myHn[4*k+2], myHn[4*k+3]);
    }
    // q (16)
    {
        float4* dst = reinterpret_cast<float4*>(g_q + (size_t)row * NACTD);
        for (int o4 = 0; o4 < 4; o4++) {
            float v0 = __ldg(fc2_b + 4*o4+0) + dot64p(fc2_w + (4*o4+0) * HDIM, hrp);
            float v1 = __ldg(fc2_b + 4*o4+1) + dot64p(fc2_w + (4*o4+1) * HDIM, hrp);
            float v2 = __ldg(fc2_b + 4*o4+2) + dot64p(fc2_w + (4*o4+2) * HDIM, hrp);
            float v3 = __ldg(fc2_b + 4*o4+3) + dot64p(fc2_w + (4*o4+3) * HDIM, hrp);
            dst[o4] = make_float4(v0, v1, v2, v3);
        }
    }
    // z1 (64, pre-BN)
    {
        float4* dst = reinterpret_cast<float4*>(g_z1 + (size_t)row * NNHD);
        for (int o4 = 0; o4 < 16; o4++) {
            float v0 = __ldg(emb_b1 + 4*o4+0) + dot64p(emb_w1 + (4*o4+0) * HDIM, hrp);
            float v1 = __ldg(emb_b1 + 4*o4+1) + dot64p(emb_w1 + (4*o4+1) * HDIM, hrp);
            float v2 = __ldg(emb_b1 + 4*o4+2) + dot64p(emb_w1 + (4*o4+2) * HDIM, hrp);
            float v3 = __ldg(emb_b1 + 4*o4+3) + dot64p(emb_w1 + (4*o4+3) * HDIM, hrp);
            dst[o4] = make_float4(v0, v1, v2, v3);
        }
    }
    // query (32), pre-scaled
    {
        const float qs = 0.17677669529663687f;
        float4* dst = reinterpret_cast<float4*>(g_query + (size_t)row * ATTD);
        for (int o4 = 0; o4 < 8; o4++) {
            float v0 = (__ldg(wq_b + 4*o4+0) + dot64p(wq_w + (4*o4+0) * HDIM, hrp)) * qs;
            float v1 = (__ldg(wq_b + 4*o4+1) + dot64p(wq_w + (4*o4+1) * HDIM, hrp)) * qs;
            float v2 = (__ldg(wq_b + 4*o4+2) + dot64p(wq_w + (4*o4+2) * HDIM, hrp)) * qs;
            float v3 = (__ldg(wq_b + 4*o4+3) + dot64p(wq_w + (4*o4+3) * HDIM, hrp)) * qs;
            dst[o4] = make_float4(v0, v1, v2, v3);
        }
    }
    // msg layer-1 h-contribution (64)
    {
        float4* dst = reinterpret_cast<float4*>(g_m1h + (size_t)row * NNHD);
        for (int o4 = 0; o4 < 16; o4++) {
            float v0 = __ldg(msg_b1 + 4*o4+0) + dot64p(msg_w1 + (4*o4+0) * 80, hrp);
            float v1 = __ldg(msg_b1 + 4*o4+1) + dot64p(msg_w1 + (4*o4+1) * 80, hrp);
            float v2 = __ldg(msg_b1 + 4*o4+2) + dot64p(msg_w1 + (4*o4+2) * 80, hrp);
            float v3 = __ldg(msg_b1 + 4*o4+3) + dot64p(msg_w1 + (4*o4+3) * 80, hrp);
            dst[o4] = make_float4(v0, v1, v2, v3);
        }
    }
}

// ---------------- K2a: BN partial sums (coalesced) ----------------
__global__ void __launch_bounds__(256) k2a_bn()
{
    __shared__ float ss[4][NNHD], sq[4][NNHD];
    const int tid = threadIdx.x;
    const int f = tid & 63;
    const int rg = tid >> 6;          // 0..3
    const int base = blockIdx.x * 256;
    float s = 0.f, q = 0.f;
    for (int r = rg; r < 256; r += 4) {
        float v = g_z1[(size_t)(base + r) * NNHD + f];
        s += v; q += v * v;
    }
    ss[rg][f] = s; sq[rg][f] = q;
    __syncthreads();
    if (tid < NNHD) {
        float S = ss[0][tid] + ss[1][tid] + ss[2][tid] + ss[3][tid];
        float Q = sq[0][tid] + sq[1][tid] + sq[2][tid] + sq[3][tid];
        g_p1[blockIdx.x * NNHD + tid] = S;
        g_p2[blockIdx.x * NNHD + tid] = Q;
    }
}

// ---------------- K2b: BN finalize ----------------
__global__ void __launch_bounds__(64) k2b_bn(const float* __restrict__ bn_g,
                                            const float* __restrict__ bn_b)
{
    const int f = threadIdx.x;
    float s = 0.f, q = 0.f;
    for (int i = 0; i < 128; i++) {
        s += g_p1[i * NNHD + f];
        q += g_p2[i * NNHD + f];
    }
    float mean = s * (1.f / (float)NROWS);
    float var  = q * (1.f / (float)NROWS) - mean * mean;
    float a = __ldg(bn_g + f) / sqrtf(var + 1e-5f);
    g_bn_a[f] = a;
    g_bn_c[f] = __ldg(bn_b + f) - a * mean;
}

// ---------------- K3: latent + keys + masked softmax ----------------
__global__ void __launch_bounds__(128) k3_latent(
    const float* __restrict__ eps,
    const float* __restrict__ emb_w2, const float* __restrict__ emb_b2,
    const float* __restrict__ wk_w, const float* __restrict__ wk_b)
{
    __shared__ float sQ[128 * 33];
    __shared__ float sAl[128 * 33];
    const int tid = threadIdx.x;
    const int row0 = blockIdx.x * 128;
    const int row = row0 + tid;
    const int b = row >> 5;
    const int i = row & 31;

    for (int idx = tid; idx < 128 * 32; idx += 128) {
        int r = idx >> 5, c = idx & 31;
        sQ[r * 33 + c] = g_query[(size_t)(row0 + r) * ATTD + c];
    }
    __syncthreads();

    // z1 -> BN affine -> lrelu -> packed regs
    u64 zp[32];
    {
        const float4* zpg = reinterpret_cast<const float4*>(g_z1 + (size_t)row * NNHD);
#pragma unroll
        for (int k = 0; k < 16; k++) {
            float4 v = __ldg(zpg + k);
            float t0 = g_bn_a[4*k+0] * v.x + g_bn_c[4*k+0]; t0 = t0 > 0.f ? t0 : 0.01f * t0;
            float t1 = g_bn_a[4*k+1] * v.y + g_bn_c[4*k+1]; t1 = t1 > 0.f ? t1 : 0.01f * t1;
            float t2 = g_bn_a[4*k+2] * v.z + g_bn_c[4*k+2]; t2 = t2 > 0.f ? t2 : 0.01f * t2;
            float t3 = g_bn_a[4*k+3] * v.w + g_bn_c[4*k+3]; t3 = t3 > 0.f ? t3 : 0.01f * t3;
            zp[2*k] = pk2(t0, t1); zp[2*k+1] = pk2(t2, t3);
        }
    }

    float* myAl = sAl + tid * 33;
    const float* qv = sQ + tid * 33;

    for (int j = 0; j < AGN; j++) {
        const float4* e4 = reinterpret_cast<const float4*>(eps + (size_t)row * DLAT + j * LDIM);
        float4* outp = reinterpret_cast<float4*>(g_lat + ((size_t)(b * AGN + j) * AGN + i) * LDIM);
        u64 latp[8];
        for (int l4 = 0; l4 < 4; l4++) {
            float4 ev = __ldg(e4 + l4);
            int d = j * LDIM + l4 * 4;
            float4 lv4;
            {
                float mu = __ldg(emb_b2 + d + 0) + dot64p(emb_w2 + (d + 0) * 64, zp);
                float lg = __ldg(emb_b2 + DLAT + d + 0) + dot64p(emb_w2 + (DLAT + d + 0) * 64, zp);
                lv4.x = mu + sqrtf(fmaxf(expf(lg), 0.002f)) * ev.x;
            }
            {
                float mu = __ldg(emb_b2 + d + 1) + dot64p(emb_w2 + (d + 1) * 64, zp);
                float lg = __ldg(emb_b2 + DLAT + d + 1) + dot64p(emb_w2 + (DLAT + d + 1) * 64, zp);
                lv4.y = mu + sqrtf(fmaxf(expf(lg), 0.002f)) * ev.y;
            }
            {
                float mu = __ldg(emb_b2 + d + 2) + dot64p(emb_w2 + (d + 2) * 64, zp);
                float lg = __ldg(emb_b2 + DLAT + d + 2) + dot64p(emb_w2 + (DLAT + d + 2) * 64, zp);
                lv4.z = mu + sqrtf(fmaxf(expf(lg), 0.002f)) * ev.z;
            }
            {
                float mu = __ldg(emb_b2 + d + 3) + dot64p(emb_w2 + (d + 3) * 64, zp);
                float lg = __ldg(emb_b2 + DLAT + d + 3) + dot64p(emb_w2 + (DLAT + d + 3) * 64, zp);
                lv4.w = mu + sqrtf(fmaxf(expf(lg), 0.002f)) * ev.w;
            }
            outp[l4] = lv4;
            latp[2*l4]   = pk2(lv4.x, lv4.y);
            latp[2*l4+1] = pk2(lv4.z, lv4.w);
        }
        // alpha[b,i,j] = query . key(lat)
        float aj = 0.f;
        for (int a = 0; a < ATTD; a++) {
            const float4* wk4 = reinterpret_cast<const float4*>(wk_w + a * LDIM);
            u64 a0 = 0ull, a1 = 0ull;
#pragma unroll
            for (int l4 = 0; l4 < 4; l4++) {
                float4 wv = __ldg(wk4 + l4);
                a0 = fma2_(pk2(wv.x, wv.y), latp[2*l4],   a0);
                a1 = fma2_(pk2(wv.z, wv.w), latp[2*l4+1], a1);
            }
            float r0,r1,r2,r3; upk2(r0,r1,a0); upk2(r2,r3,a1);
            float kacc = __ldg(wk_b + a) + ((r0+r1)+(r2+r3));
            aj = fmaf(qv[a], kacc, aj);
        }
        myAl[j] = aj;
    }

    // masked softmax over j
    myAl[i] = -1e9f;
    float m = -3.4e38f;
    for (int j = 0; j < AGN; j++) m = fmaxf(m, myAl[j]);
    float ssum = 0.f;
    for (int j = 0; j < AGN; j++) { float e = expf(myAl[j] - m); myAl[j] = e; ssum += e; }
    float inv = 1.f / ssum;
    for (int j = 0; j < AGN; j++)
        g_alpha[(size_t)(b * AGN + j) * AGN + i] = myAl[j] * inv;
}

// ---------------- K4: message MLP + weighted aggregate + q add ----------------
// Block = one batch b (1024 blocks, 256 threads, 8 warps; warp w owns j = w+8k).
// Linearity: agg[j] = W2 . (sum_i alpha_ij * lrelu(s_ij)) + (sum_i alpha_ij) * b2
__global__ void __launch_bounds__(256) k4_msg(
    const float* __restrict__ msg_w1,
    const float* __restrict__ msg_w2, const float* __restrict__ msg_b2,
    float* __restrict__ ret_q)
{
    __shared__ float sW2[16 * 68];     // padded rows
    __shared__ float sB2[16];
    __shared__ float sU[8][68];        // per-warp u vector
    const int tid = threadIdx.x;
    const int w = tid >> 5;
    const int lane = tid & 31;
    const int b = blockIdx.x;

    for (int idx = tid; idx < 16 * 64; idx += 256) {
        int r = idx >> 6, c = idx & 63;
        sW2[r * 68 + c] = __ldg(msg_w2 + idx);
    }
    if (tid < 16) sB2[tid] = __ldg(msg_b2 + tid);

    // per-lane W1 latent rows (o0 = lane, o1 = lane+32), cols 64..79, packed
    u64 w1a[8], w1b[8];
    {
        const float4* p0 = reinterpret_cast<const float4*>(msg_w1 + lane * 80 + 64);
        const float4* p1 = reinterpret_cast<const float4*>(msg_w1 + (lane + 32) * 80 + 64);
#pragma unroll
        for (int k = 0; k < 4; k++) {
            float4 v0 = __ldg(p0 + k), v1 = __ldg(p1 + k);
            w1a[2*k] = pk2(v0.x, v0.y); w1a[2*k+1] = pk2(v0.z, v0.w);
            w1b[2*k] = pk2(v1.x, v1.y); w1b[2*k+1] = pk2(v1.z, v1.w);
        }
    }
    __syncthreads();

#pragma unroll
    for (int jj = 0; jj < 4; jj++) {
        const int j = w + jj * 8;
        const int bj = b * AGN + j;
        const float m0 = __ldg(g_m1h + (size_t)bj * NNHD + lane);
        const float m1 = __ldg(g_m1h + (size_t)bj * NNHD + 32 + lane);
        const float* latbase = g_lat + (size_t)bj * AGN * LDIM;
        const float* alb = g_alpha + (size_t)bj * AGN;
        float u0 = 0.f, u1 = 0.f, sa = 0.f;

        for (int i = 0; i < AGN; i++) {
            const float4* l4 = reinterpret_cast<const float4*>(latbase + i * LDIM);
            float4 A = __ldg(l4), B = __ldg(l4+1), C = __ldg(l4+2), D = __ldg(l4+3);
            u64 z0 = pk2(A.x,A.y), z1 = pk2(A.z,A.w), z2 = pk2(B.x,B.y), z3 = pk2(B.z,B.w);
            u64 z4 = pk2(C.x,C.y), z5 = pk2(C.z,C.w), z6 = pk2(D.x,D.y), z7 = pk2(D.z,D.w);
            u64 a0 = 0ull, a1 = 0ull, b0 = 0ull, b1 = 0ull;
            a0 = fma2_(w1a[0], z0, a0); a1 = fma2_(w1a[1], z1, a1);
            b0 = fma2_(w1b[0], z0, b0); b1 = fma2_(w1b[1], z1, b1);
            a0 = fma2_(w1a[2], z2, a0); a1 = fma2_(w1a[3], z3, a1);
            b0 = fma2_(w1b[2], z2, b0); b1 = fma2_(w1b[3], z3, b1);
            a0 = fma2_(w1a[4], z4, a0); a1 = fma2_(w1a[5], z5, a1);
            b0 = fma2_(w1b[4], z4, b0); b1 = fma2_(w1b[5], z5, b1);
            a0 = fma2_(w1a[6], z6, a0); a1 = fma2_(w1a[7], z7, a1);
            b0 = fma2_(w1b[6], z6, b0); b1 = fma2_(w1b[7], z7, b1);
            float r0,r1,r2,r3; upk2(r0,r1,a0); upk2(r2,r3,a1);
            float s0 = m0 + ((r0+r1)+(r2+r3));
            upk2(r0,r1,b0); upk2(r2,r3,b1);
            float s1 = m1 + ((r0+r1)+(r2+r3));
            s0 = s0 > 0.f ? s0 : 0.01f * s0;
            s1 = s1 > 0.f ? s1 : 0.01f * s1;
            float al = __ldg(alb + i);
            sa += al;
            u0 = fmaf(al, s0, u0);
            u1 = fmaf(al, s1, u1);
        }
        sU[w][lane] = u0; sU[w][32 + lane] = u1;
        __syncwarp();
        if (lane < 16) {
            float acc = __ldg(g_q + (size_t)bj * NACTD + lane) + sa * sB2[lane];
            const float* w2r = sW2 + lane * 68;
            const float* uv = sU[w];
            float c0 = 0.f, c1 = 0.f;
#pragma unroll
            for (int o = 0; o < 64; o += 2) {
                c0 = fmaf(w2r[o],   uv[o],   c0);
                c1 = fmaf(w2r[o+1], uv[o+1], c1);
            }
            ret_q[(size_t)bj * NACTD + lane] = acc + c0 + c1;
        }
        __syncwarp();
    }
}

// ---------------- host launcher ----------------
extern "C" void kernel_launch(void* const* d_in, const int* in_sizes, int n_in,
                              void* d_out, int out_size)
{
    (void)in_sizes; (void)n_in; (void)out_size;
    const float* inputs  = (const float*)d_in[0];
    const float* hidden  = (const float*)d_in[1];
    const float* eps     = (const float*)d_in[2];
    const float* fc1_w   = (const float*)d_in[3];
    const float* fc1_b   = (const float*)d_in[4];
    const float* gru_wih = (const float*)d_in[5];
    const float* gru_whh = (const float*)d_in[6];
    const float* gru_bih = (const float*)d_in[7];
    const float* gru_bhh = (const float*)d_in[8];
    const float* fc2_w   = (const float*)d_in[9];
    const float* fc2_b   = (const float*)d_in[10];
    const float* emb_w1  = (const float*)d_in[11];
    const float* emb_b1  = (const float*)d_in[12];
    const float* bn_g    = (const float*)d_in[13];
    const float* bn_b    = (const float*)d_in[14];
    const float* emb_w2  = (const float*)d_in[15];
    const float* emb_b2  = (const float*)d_in[16];
    const float* msg_w1  = (const float*)d_in[17];
    const float* msg_b1  = (const float*)d_in[18];
    const float* msg_w2  = (const float*)d_in[19];
    const float* msg_b2  = (const float*)d_in[20];
    const float* wq_w    = (const float*)d_in[21];
    const float* wq_b    = (const float*)d_in[22];
    const float* wk_w    = (const float*)d_in[23];
    const float* wk_b    = (const float*)d_in[24];

    float* out   = (float*)d_out;
    float* ret_q = out;                          // [32768,16]
    float* h_out = out + (size_t)NROWS * NACTD;  // [32768,64]

    const int K1_SMEM = 3 * 128 * 65 * sizeof(float);  // 99,840 B
    cudaFuncSetAttribute(k1_trunk, cudaFuncAttributeMaxDynamicSharedMemorySize, K1_SMEM);

    k1_trunk<<<NROWS / 128, 128, K1_SMEM>>>(
        inputs, hidden, fc1_w, fc1_b, gru_wih, gru_whh, gru_bih, gru_bhh,
        fc2_w, fc2_b, emb_w1, emb_b1, wq_w, wq_b, msg_w1, msg_b1, h_out);

    k2a_bn<<<128, 256>>>();
    k2b_bn<<<1, 64>>>(bn_g, bn_b);

    k3_latent<<<NROWS / 128, 128>>>(eps, emb_w2, emb_b2, wk_w, wk_b);

    k4_msg<<<BSZ, 256>>>(msg_w1, msg_w2, msg_b2, ret_q);
}

// round 3
// speedup vs baseline: 2.4275x; 2.4275x over previous
#include <cuda_runtime.h>

#define NROWS 32768
#define BSZ   1024
#define AGN   32
#define IND   96
#define HDIM  64
#define NNHD  64
#define ATTD  32
#define NACTD 16
#define LDIM  16
#define DLAT  512

typedef unsigned long long u64;

// ---------------- scratch (device globals) ----------------
__device__ float g_z1[NROWS * NNHD];
__device__ float g_q[NROWS * NACTD];
__device__ float g_query[NROWS * ATTD];
__device__ float g_m1h[NROWS * NNHD];
__device__ float g_lat[BSZ * AGN * AGN * LDIM];   // [b][j][i][l]
__device__ float g_alpha[BSZ * AGN * AGN];        // [b][j][i]
__device__ float g_bn_a[NNHD];
__device__ float g_bn_c[NNHD];
__device__ float g_p1[128 * NNHD];
__device__ float g_p2[128 * NNHD];

// ---------------- packed f32x2 helpers ----------------
__device__ __forceinline__ u64 pk2(float lo, float hi) {
    u64 r; asm("mov.b64 %0, {%1, %2};" : "=l"(r) : "f"(lo), "f"(hi)); return r;
}
__device__ __forceinline__ void upk2(float& lo, float& hi, u64 v) {
    asm("mov.b64 {%0, %1}, %2;" : "=f"(lo), "=f"(hi) : "l"(v));
}
__device__ __forceinline__ u64 fma2_(u64 a, u64 b, u64 c) {
    u64 d; asm("fma.rn.f32x2 %0, %1, %2, %3;" : "=l"(d) : "l"(a), "l"(b), "l"(c)); return d;
}
__device__ __forceinline__ float red4(u64 a0, u64 a1, u64 a2, u64 a3) {
    float r0,r1,r2,r3,r4,r5,r6,r7;
    upk2(r0,r1,a0); upk2(r2,r3,a1); upk2(r4,r5,a2); upk2(r6,r7,a3);
    return ((r0+r1)+(r2+r3))+((r4+r5)+(r6+r7));
}

// dot products with weights in SHARED memory (LDS.128 broadcast)
__device__ __forceinline__ float dot64s(const float* w, const u64 (&z)[32]) {
    const float4* w4 = reinterpret_cast<const float4*>(w);
    u64 a0=0ull, a1=0ull, a2=0ull, a3=0ull;
#pragma unroll
    for (int k = 0; k < 16; k++) {
        float4 u = w4[k];
        u64 w0 = pk2(u.x, u.y), w1 = pk2(u.z, u.w);
        if (k & 1) { a2 = fma2_(w0, z[2*k], a2); a3 = fma2_(w1, z[2*k+1], a3); }
        else       { a0 = fma2_(w0, z[2*k], a0); a1 = fma2_(w1, z[2*k+1], a1); }
    }
    return red4(a0,a1,a2,a3);
}
__device__ __forceinline__ float dot96s(const float* w, const u64 (&z)[48]) {
    const float4* w4 = reinterpret_cast<const float4*>(w);
    u64 a0=0ull, a1=0ull, a2=0ull, a3=0ull;
#pragma unroll
    for (int k = 0; k < 24; k++) {
        float4 u = w4[k];
        u64 w0 = pk2(u.x, u.y), w1 = pk2(u.z, u.w);
        if (k & 1) { a2 = fma2_(w0, z[2*k], a2); a3 = fma2_(w1, z[2*k+1], a3); }
        else       { a0 = fma2_(w0, z[2*k], a0); a1 = fma2_(w1, z[2*k+1], a1); }
    }
    return red4(a0,a1,a2,a3);
}

__device__ __forceinline__ void cload(float* dst, const float* __restrict__ src,
                                      int n4, int tid) {
    float4* d = reinterpret_cast<float4*>(dst);
    const float4* s = reinterpret_cast<const float4*>(src);
    for (int i = tid; i < n4; i += 128) d[i] = __ldg(s + i);
}

__device__ __forceinline__ float sigmoidf_(float x) { return 1.f / (1.f + expf(-x)); }

// ---------------- K1: fused trunk, smem-pipelined weights ----------------
__global__ void __launch_bounds__(128) k1_trunk(
    const float* __restrict__ inp, const float* __restrict__ h0,
    const float* __restrict__ fc1_w, const float* __restrict__ fc1_b,
    const float* __restrict__ wih, const float* __restrict__ whh,
    const float* __restrict__ bih, const float* __restrict__ bhh,
    const float* __restrict__ fc2_w, const float* __restrict__ fc2_b,
    const float* __restrict__ emb_w1, const float* __restrict__ emb_b1,
    const float* __restrict__ wq_w, const float* __restrict__ wq_b,
    const float* __restrict__ msg_w1, const float* __restrict__ msg_b1,
    float* __restrict__ h_out)
{
    extern __shared__ float sm1[];
    float* sX  = sm1;               // 128*65 scalar x scratch
    float* sH  = sm1 + 128 * 65;    // 128*65 h (in-place old->new)
    float* wb0 = sm1 + 2 * 128 * 65;
    float* wb1 = wb0 + 3072;
    const int tid = threadIdx.x;
    const int row = blockIdx.x * 128 + tid;
    float* myX = sX + tid * 65;
    float* myH = sH + tid * 65;

    // input row packed
    u64 xinp[48];
    {
        const float4* ip = reinterpret_cast<const float4*>(inp + (size_t)row * IND);
#pragma unroll
        for (int k = 0; k < 24; k++) {
            float4 v = __ldg(ip + k);
            xinp[2*k] = pk2(v.x, v.y); xinp[2*k+1] = pk2(v.z, v.w);
        }
    }
    // h0 packed + scalar copy into sH
    u64 hrp[32];
    {
        const float4* hp = reinterpret_cast<const float4*>(h0 + (size_t)row * HDIM);
#pragma unroll
        for (int k = 0; k < 16; k++) {
            float4 v = __ldg(hp + k);
            hrp[2*k] = pk2(v.x, v.y); hrp[2*k+1] = pk2(v.z, v.w);
            myH[4*k] = v.x; myH[4*k+1] = v.y; myH[4*k+2] = v.z; myH[4*k+3] = v.w;
        }
    }

    // ---- pipeline: fc1(2 chunks of 32 rows) ----
    cload(wb0, fc1_w, 768, tid);
    __syncthreads();
    {   // fc1 chunk0 from wb0; prefetch chunk1 -> wb1
        cload(wb1, fc1_w + 3072, 768, tid);
        for (int oo = 0; oo < 32; oo++)
            myX[oo] = fmaxf(__ldg(fc1_b + oo) + dot96s(wb0 + oo * 96, xinp), 0.f);
        __syncthreads();
    }
    {   // fc1 chunk1 from wb1; prefetch GRU g=0 -> wb0
        {
            int o0 = 0;
            cload(wb0 + 0*512, wih + (o0)*64,       128, tid);
            cload(wb0 + 1*512, wih + (64+o0)*64,    128, tid);
            cload(wb0 + 2*512, wih + (128+o0)*64,   128, tid);
            cload(wb0 + 3*512, whh + (o0)*64,       128, tid);
            cload(wb0 + 4*512, whh + (64+o0)*64,    128, tid);
            cload(wb0 + 5*512, whh + (128+o0)*64,   128, tid);
        }
        for (int oo = 0; oo < 32; oo++)
            myX[32+oo] = fmaxf(__ldg(fc1_b + 32 + oo) + dot96s(wb1 + oo * 96, xinp), 0.f);
        __syncthreads();
    }
    u64 xrp[32];
#pragma unroll
    for (int k = 0; k < 32; k++) xrp[k] = pk2(myX[2*k], myX[2*k+1]);

    // ---- GRU: 8 chunks of 8 outputs ----
    for (int g = 0; g < 8; g++) {
        float* w  = (g & 1) ? wb1 : wb0;
        float* nx = (g & 1) ? wb0 : wb1;
        if (g < 7) {
            int o0 = (g + 1) * 8;
            cload(nx + 0*512, wih + (o0)*64,       128, tid);
            cload(nx + 1*512, wih + (64+o0)*64,    128, tid);
            cload(nx + 2*512, wih + (128+o0)*64,   128, tid);
            cload(nx + 3*512, whh + (o0)*64,       128, tid);
            cload(nx + 4*512, whh + (64+o0)*64,    128, tid);
            cload(nx + 5*512, whh + (128+o0)*64,   128, tid);
        } else {
            cload(nx, fc2_w, 256, tid);  // heads chunk: fc2 -> wb0 (g=7 odd)
        }
        for (int oo = 0; oo < 8; oo++) {
            int o = g * 8 + oo;
            float ar = __ldg(bih + o) + __ldg(bhh + o)
                     + dot64s(w + oo*64,        xrp) + dot64s(w + 1536 + oo*64, hrp);
            float az = __ldg(bih + 64 + o) + __ldg(bhh + 64 + o)
                     + dot64s(w + 512 + oo*64,  xrp) + dot64s(w + 2048 + oo*64, hrp);
            float ai = __ldg(bih + 128 + o) + dot64s(w + 1024 + oo*64, xrp);
            float ah = __ldg(bhh + 128 + o) + dot64s(w + 2560 + oo*64, hrp);
            float r = sigmoidf_(ar);
            float z = sigmoidf_(az);
            float n = tanhf(ai + r * ah);
            myH[o] = (1.f - z) * n + z * myH[o];   // in-place: reads old h[o]
        }
        __syncthreads();
    }
#pragma unroll
    for (int k = 0; k < 32; k++) hrp[k] = pk2(myH[2*k], myH[2*k+1]);
    {
        float4* hop = reinterpret_cast<float4*>(h_out + (size_t)row * HDIM);
#pragma unroll
        for (int k = 0; k < 16; k++)
            hop[k] = make_float4(myH[4*k], myH[4*k+1], myH[4*k+2], myH[4*k+3]);
    }

    // ---- heads pipeline. fc2 currently in wb0. ----
    {   // q from wb0; prefetch emb_w1 rows 0..31 -> wb1
        cload(wb1, emb_w1, 512, tid);
        float4* dst = reinterpret_cast<float4*>(g_q + (size_t)row * NACTD);
        for (int o4 = 0; o4 < 4; o4++) {
            float v0 = __ldg(fc2_b + 4*o4+0) + dot64s(wb0 + (4*o4+0)*64, hrp);
            float v1 = __ldg(fc2_b + 4*o4+1) + dot64s(wb0 + (4*o4+1)*64, hrp);
            float v2 = __ldg(fc2_b + 4*o4+2) + dot64s(wb0 + (4*o4+2)*64, hrp);
            float v3 = __ldg(fc2_b + 4*o4+3) + dot64s(wb0 + (4*o4+3)*64, hrp);
            dst[o4] = make_float4(v0, v1, v2, v3);
        }
        __syncthreads();
    }
    {   // z1 rows 0..31 from wb1; prefetch emb_w1 rows 32..63 -> wb0
        cload(wb0, emb_w1 + 2048, 512, tid);
        float4* dst = reinterpret_cast<float4*>(g_z1 + (size_t)row * NNHD);
        for (int o4 = 0; o4 < 8; o4++) {
            float v0 = __ldg(emb_b1 + 4*o4+0) + dot64s(wb1 + (4*o4+0)*64, hrp);
            float v1 = __ldg(emb_b1 + 4*o4+1) + dot64s(wb1 + (4*o4+1)*64, hrp);
            float v2 = __ldg(emb_b1 + 4*o4+2) + dot64s(wb1 + (4*o4+2)*64, hrp);
            float v3 = __ldg(emb_b1 + 4*o4+3) + dot64s(wb1 + (4*o4+3)*64, hrp);
            dst[o4] = make_float4(v0, v1, v2, v3);
        }
        __syncthreads();
    }
    {   // z1 rows 32..63 from wb0; prefetch wq -> wb1
        cload(wb1, wq_w, 512, tid);
        float4* dst = reinterpret_cast<float4*>(g_z1 + (size_t)row * NNHD) + 8;
        for (int o4 = 0; o4 < 8; o4++) {
            float v0 = __ldg(emb_b1 + 32 + 4*o4+0) + dot64s(wb0 + (4*o4+0)*64, hrp);
            float v1 = __ldg(emb_b1 + 32 + 4*o4+1) + dot64s(wb0 + (4*o4+1)*64, hrp);
            float v2 = __ldg(emb_b1 + 32 + 4*o4+2) + dot64s(wb0 + (4*o4+2)*64, hrp);
            float v3 = __ldg(emb_b1 + 32 + 4*o4+3) + dot64s(wb0 + (4*o4+3)*64, hrp);
            dst[o4] = make_float4(v0, v1, v2, v3);
        }
        __syncthreads();
    }
    {   // query from wb1 (scaled); prefetch msg_w1 rows 0..31 -> wb0
        cload(wb0, msg_w1, 640, tid);
        const float qs = 0.17677669529663687f;
        float4* dst = reinterpret_cast<float4*>(g_query + (size_t)row * ATTD);
        for (int o4 = 0; o4 < 8; o4++) {
            float v0 = (__ldg(wq_b + 4*o4+0) + dot64s(wb1 + (4*o4+0)*64, hrp)) * qs;
            float v1 = (__ldg(wq_b + 4*o4+1) + dot64s(wb1 + (4*o4+1)*64, hrp)) * qs;
            float v2 = (__ldg(wq_b + 4*o4+2) + dot64s(wb1 + (4*o4+2)*64, hrp)) * qs;
            float v3 = (__ldg(wq_b + 4*o4+3) + dot64s(wb1 + (4*o4+3)*64, hrp)) * qs;
            dst[o4] = make_float4(v0, v1, v2, v3);
        }
        __syncthreads();
    }
    {   // m1h rows 0..31 from wb0; prefetch msg_w1 rows 32..63 -> wb1
        cload(wb1, msg_w1 + 2560, 640, tid);
        float4* dst = reinterpret_cast<float4*>(g_m1h + (size_t)row * NNHD);
        for (int o4 = 0; o4 < 8; o4++) {
            float v0 = __ldg(msg_b1 + 4*o4+0) + dot64s(wb0 + (4*o4+0)*80, hrp);
            float v1 = __ldg(msg_b1 + 4*o4+1) + dot64s(wb0 + (4*o4+1)*80, hrp);
            float v2 = __ldg(msg_b1 + 4*o4+2) + dot64s(wb0 + (4*o4+2)*80, hrp);
            float v3 = __ldg(msg_b1 + 4*o4+3) + dot64s(wb0 + (4*o4+3)*80, hrp);
            dst[o4] = make_float4(v0, v1, v2, v3);
        }
        __syncthreads();
    }
    {   // m1h rows 32..63 from wb1
        float4* dst = reinterpret_cast<float4*>(g_m1h + (size_t)row * NNHD) + 8;
        for (int o4 = 0; o4 < 8; o4++) {
            float v0 = __ldg(msg_b1 + 32 + 4*o4+0) + dot64s(wb1 + (4*o4+0)*80, hrp);
            float v1 = __ldg(msg_b1 + 32 + 4*o4+1) + dot64s(wb1 + (4*o4+1)*80, hrp);
            float v2 = __ldg(msg_b1 + 32 + 4*o4+2) + dot64s(wb1 + (4*o4+2)*80, hrp);
            float v3 = __ldg(msg_b1 + 32 + 4*o4+3) + dot64s(wb1 + (4*o4+3)*80, hrp);
            dst[o4] = make_float4(v0, v1, v2, v3);
        }
    }
}

// ---------------- K2a/K2b: BN statistics ----------------
__global__ void __launch_bounds__(256) k2a_bn()
{
    __shared__ float ss[4][NNHD], sq[4][NNHD];
    const int tid = threadIdx.x;
    const int f = tid & 63;
    const int rg = tid >> 6;
    const int base = blockIdx.x * 256;
    float s = 0.f, q = 0.f;
    for (int r = rg; r < 256; r += 4) {
        float v = g_z1[(size_t)(base + r) * NNHD + f];
        s += v; q += v * v;
    }
    ss[rg][f] = s; sq[rg][f] = q;
    __syncthreads();
    if (tid < NNHD) {
        g_p1[blockIdx.x * NNHD + tid] = ss[0][tid] + ss[1][tid] + ss[2][tid] + ss[3][tid];
        g_p2[blockIdx.x * NNHD + tid] = sq[0][tid] + sq[1][tid] + sq[2][tid] + sq[3][tid];
    }
}
__global__ void __launch_bounds__(64) k2b_bn(const float* __restrict__ bn_g,
                                            const float* __restrict__ bn_b)
{
    const int f = threadIdx.x;
    float s = 0.f, q = 0.f;
    for (int i = 0; i < 128; i++) { s += g_p1[i * NNHD + f]; q += g_p2[i * NNHD + f]; }
    float mean = s * (1.f / (float)NROWS);
    float var  = q * (1.f / (float)NROWS) - mean * mean;
    float a = __ldg(bn_g + f) / sqrtf(var + 1e-5f);
    g_bn_a[f] = a;
    g_bn_c[f] = __ldg(bn_b + f) - a * mean;
}

// ---------------- K3a: latent GEMM + fused alpha + softmax ----------------
// Thread = one row (b,i). emb_w2 streamed via smem ping-pong chunks of 32 d
// (mu rows + matching lg rows). Alpha via folded qk = Wk^T q accumulated as
// latent is produced. Softmax at tail.
__global__ void __launch_bounds__(128) k3a_latent(
    const float* __restrict__ eps,
    const float* __restrict__ emb_w2, const float* __restrict__ emb_b2,
    const float* __restrict__ wk_w, const float* __restrict__ wk_b)
{
    extern __shared__ float sm3[];
    float* wbuf0 = sm3;            // 4096: [0..2047]=mu rows, [2048..4095]=lg rows
    float* wbuf1 = sm3 + 4096;
    float* swk   = sm3 + 8192;     // 512: wk_w[32][16]
    float* sAl   = sm3 + 8704;     // 128*33
    const int tid = threadIdx.x;
    const int row = blockIdx.x * 128 + tid;
    const int b = row >> 5;
    const int i = row & 31;

    // z1 -> BN affine -> lrelu -> packed regs
    u64 zp[32];
    {
        const float4* zpg = reinterpret_cast<const float4*>(g_z1 + (size_t)row * NNHD);
#pragma unroll
        for (int k = 0; k < 16; k++) {
            float4 v = __ldg(zpg + k);
            float t0 = g_bn_a[4*k+0] * v.x + g_bn_c[4*k+0]; t0 = t0 > 0.f ? t0 : 0.01f * t0;
            float t1 = g_bn_a[4*k+1] * v.y + g_bn_c[4*k+1]; t1 = t1 > 0.f ? t1 : 0.01f * t1;
            float t2 = g_bn_a[4*k+2] * v.z + g_bn_c[4*k+2]; t2 = t2 > 0.f ? t2 : 0.01f * t2;
            float t3 = g_bn_a[4*k+3] * v.w + g_bn_c[4*k+3]; t3 = t3 > 0.f ? t3 : 0.01f * t3;
            zp[2*k] = pk2(t0, t1); zp[2*k+1] = pk2(t2, t3);
        }
    }

    // prologue: chunk 0 + wk
    cload(wbuf0,        emb_w2,            512, tid);
    cload(wbuf0 + 2048, emb_w2 + 512 * 64, 512, tid);
    cload(swk, wk_w, 128, tid);
    __syncthreads();

    // folded query: qk[l] = sum_a q[a]*wk[a][l];  qb = q . wk_b
    float qk[16];
#pragma unroll
    for (int l = 0; l < 16; l++) qk[l] = 0.f;
    float qb = 0.f;
    {
        const float4* qp = reinterpret_cast<const float4*>(g_query + (size_t)row * ATTD);
#pragma unroll
        for (int k = 0; k < 8; k++) {
            float4 v = __ldg(qp + k);
            float qa[4] = {v.x, v.y, v.z, v.w};
#pragma unroll
            for (int u = 0; u < 4; u++) {
                int a = 4*k + u;
#pragma unroll
                for (int l = 0; l < 16; l++) qk[l] = fmaf(qa[u], swk[a*16 + l], qk[l]);
                qb = fmaf(qa[u], __ldg(wk_b + a), qb);
            }
        }
    }

    float* myAl = sAl + tid * 33;
    const float* epsrow = eps + (size_t)row * DLAT;

    for (int c = 0; c < 16; c++) {
        float* w = (c & 1) ? wbuf1 : wbuf0;
        if (c < 15) {
            float* nw = (c & 1) ? wbuf0 : wbuf1;
            int d0n = (c + 1) * 32;
            cload(nw,        emb_w2 + d0n * 64,         512, tid);
            cload(nw + 2048, emb_w2 + (512 + d0n) * 64, 512, tid);
        }
        const int d0 = c * 32;
        float accA = qb, accB = qb;
#pragma unroll
        for (int g = 0; g < 8; g++) {
            float4 e4 = __ldg(reinterpret_cast<const float4*>(epsrow + d0 + g * 4));
            float ev[4] = {e4.x, e4.y, e4.z, e4.w};
            float lat[4];
#pragma unroll
            for (int u = 0; u < 4; u++) {
                int dd = g * 4 + u;
                float mu = __ldg(emb_b2 + d0 + dd) + dot64s(w + dd * 64, zp);
                float lg = __ldg(emb_b2 + 512 + d0 + dd) + dot64s(w + 2048 + dd * 64, zp);
                lat[u] = mu + sqrtf(fmaxf(expf(lg), 0.002f)) * ev[u];
            }
            const int j  = (d0 + g * 4) >> 4;       // 2c or 2c+1
            const int l0 = (g * 4) & 15;
            *reinterpret_cast<float4*>(g_lat + ((size_t)((b * AGN + j) * AGN + i)) * LDIM + l0)
                = make_float4(lat[0], lat[1], lat[2], lat[3]);
            float p = qk[l0+0]*lat[0] + qk[l0+1]*lat[1] + qk[l0+2]*lat[2] + qk[l0+3]*lat[3];
            if (g < 4) accA += p; else accB += p;
        }
        myAl[2*c]   = accA;
        myAl[2*c+1] = accB;
        __syncthreads();
    }

    // masked softmax over j
    myAl[i] = -1e9f;
    float m = -3.4e38f;
    for (int j = 0; j < AGN; j++) m = fmaxf(m, myAl[j]);
    float ssum = 0.f;
    for (int j = 0; j < AGN; j++) { float e = expf(myAl[j] - m); myAl[j] = e; ssum += e; }
    float inv = 1.f / ssum;
    for (int j = 0; j < AGN; j++)
        g_alpha[(size_t)(b * AGN + j) * AGN + i] = myAl[j] * inv;
}

// ---------------- K4: message MLP + weighted aggregate + q add ----------------
__global__ void __launch_bounds__(256) k4_msg(
    const float* __restrict__ msg_w1,
    const float* __restrict__ msg_w2, const float* __restrict__ msg_b2,
    float* __restrict__ ret_q)
{
    __shared__ float sW2[16 * 68];
    __shared__ float sB2[16];
    __shared__ float sU[8][68];
    const int tid = threadIdx.x;
    const int w = tid >> 5;
    const int lane = tid & 31;
    const int b = blockIdx.x;

    for (int idx = tid; idx < 16 * 64; idx += 256) {
        int r = idx >> 6, c = idx & 63;
        sW2[r * 68 + c] = __ldg(msg_w2 + idx);
    }
    if (tid < 16) sB2[tid] = __ldg(msg_b2 + tid);

    u64 w1a[8], w1b[8];
    {
        const float4* p0 = reinterpret_cast<const float4*>(msg_w1 + lane * 80 + 64);
        const float4* p1 = reinterpret_cast<const float4*>(msg_w1 + (lane + 32) * 80 + 64);
#pragma unroll
        for (int k = 0; k < 4; k++) {
            float4 v0 = __ldg(p0 + k), v1 = __ldg(p1 + k);
            w1a[2*k] = pk2(v0.x, v0.y); w1a[2*k+1] = pk2(v0.z, v0.w);
            w1b[2*k] = pk2(v1.x, v1.y); w1b[2*k+1] = pk2(v1.z, v1.w);
        }
    }
    __syncthreads();

#pragma unroll
    for (int jj = 0; jj < 4; jj++) {
        const int j = w + jj * 8;
        const int bj = b * AGN + j;
        const float m0 = __ldg(g_m1h + (size_t)bj * NNHD + lane);
        const float m1 = __ldg(g_m1h + (size_t)bj * NNHD + 32 + lane);
        const float* latbase = g_lat + (size_t)bj * AGN * LDIM;
        const float* alb = g_alpha + (size_t)bj * AGN;
        float u0 = 0.f, u1 = 0.f, sa = 0.f;

        for (int i = 0; i < AGN; i++) {
            const float4* l4 = reinterpret_cast<const float4*>(latbase + i * LDIM);
            float4 A = __ldg(l4), B = __ldg(l4+1), C = __ldg(l4+2), D = __ldg(l4+3);
            u64 z0 = pk2(A.x,A.y), z1 = pk2(A.z,A.w), z2 = pk2(B.x,B.y), z3 = pk2(B.z,B.w);
            u64 z4 = pk2(C.x,C.y), z5 = pk2(C.z,C.w), z6 = pk2(D.x,D.y), z7 = pk2(D.z,D.w);
            u64 a0 = 0ull, a1 = 0ull, b0 = 0ull, b1 = 0ull;
            a0 = fma2_(w1a[0], z0, a0); a1 = fma2_(w1a[1], z1, a1);
            b0 = fma2_(w1b[0], z0, b0); b1 = fma2_(w1b[1], z1, b1);
            a0 = fma2_(w1a[2], z2, a0); a1 = fma2_(w1a[3], z3, a1);
            b0 = fma2_(w1b[2], z2, b0); b1 = fma2_(w1b[3], z3, b1);
            a0 = fma2_(w1a[4], z4, a0); a1 = fma2_(w1a[5], z5, a1);
            b0 = fma2_(w1b[4], z4, b0); b1 = fma2_(w1b[5], z5, b1);
            a0 = fma2_(w1a[6], z6, a0); a1 = fma2_(w1a[7], z7, a1);
            b0 = fma2_(w1b[6], z6, b0); b1 = fma2_(w1b[7], z7, b1);
            float r0,r1,r2,r3; upk2(r0,r1,a0); upk2(r2,r3,a1);
            float s0 = m0 + ((r0+r1)+(r2+r3));
            upk2(r0,r1,b0); upk2(r2,r3,b1);
            float s1 = m1 + ((r0+r1)+(r2+r3));
            s0 = s0 > 0.f ? s0 : 0.01f * s0;
            s1 = s1 > 0.f ? s1 : 0.01f * s1;
            float al = __ldg(alb + i);
            sa += al;
            u0 = fmaf(al, s0, u0);
            u1 = fmaf(al, s1, u1);
        }
        sU[w][lane] = u0; sU[w][32 + lane] = u1;
        __syncwarp();
        if (lane < 16) {
            float acc = __ldg(g_q + (size_t)bj * NACTD + lane) + sa * sB2[lane];
            const float* w2r = sW2 + lane * 68;
            const float* uv = sU[w];
            float c0 = 0.f, c1 = 0.f;
#pragma unroll
            for (int o = 0; o < 64; o += 2) {
                c0 = fmaf(w2r[o],   uv[o],   c0);
                c1 = fmaf(w2r[o+1], uv[o+1], c1);
            }
            ret_q[(size_t)bj * NACTD + lane] = acc + c0 + c1;
        }
        __syncwarp();
    }
}

// ---------------- host launcher ----------------
extern "C" void kernel_launch(void* const* d_in, const int* in_sizes, int n_in,
                              void* d_out, int out_size)
{
    (void)in_sizes; (void)n_in; (void)out_size;
    const float* inputs  = (const float*)d_in[0];
    const float* hidden  = (const float*)d_in[1];
    const float* eps     = (const float*)d_in[2];
    const float* fc1_w   = (const float*)d_in[3];
    const float* fc1_b   = (const float*)d_in[4];
    const float* gru_wih = (const float*)d_in[5];
    const float* gru_whh = (const float*)d_in[6];
    const float* gru_bih = (const float*)d_in[7];
    const float* gru_bhh = (const float*)d_in[8];
    const float* fc2_w   = (const float*)d_in[9];
    const float* fc2_b   = (const float*)d_in[10];
    const float* emb_w1  = (const float*)d_in[11];
    const float* emb_b1  = (const float*)d_in[12];
    const float* bn_g    = (const float*)d_in[13];
    const float* bn_b    = (const float*)d_in[14];
    const float* emb_w2  = (const float*)d_in[15];
    const float* emb_b2  = (const float*)d_in[16];
    const float* msg_w1  = (const float*)d_in[17];
    const float* msg_b1  = (const float*)d_in[18];
    const float* msg_w2  = (const float*)d_in[19];
    const float* msg_b2  = (const float*)d_in[20];
    const float* wq_w    = (const float*)d_in[21];
    const float* wq_b    = (const float*)d_in[22];
    const float* wk_w    = (const float*)d_in[23];
    const float* wk_b    = (const float*)d_in[24];

    float* out   = (float*)d_out;
    float* ret_q = out;                          // [32768,16]
    float* h_out = out + (size_t)NROWS * NACTD;  // [32768,64]

    const int K1_SMEM = (2 * 128 * 65 + 2 * 3072) * sizeof(float);   // 91,136 B
    const int K3_SMEM = (2 * 4096 + 512 + 128 * 33) * sizeof(float); // 51,712 B
    cudaFuncSetAttribute(k1_trunk,   cudaFuncAttributeMaxDynamicSharedMemorySize, K1_SMEM);
    cudaFuncSetAttribute(k3a_latent, cudaFuncAttributeMaxDynamicSharedMemorySize, K3_SMEM);

    k1_trunk<<<NROWS / 128, 128, K1_SMEM>>>(
        inputs, hidden, fc1_w, fc1_b, gru_wih, gru_whh, gru_bih, gru_bhh,
        fc2_w, fc2_b, emb_w1, emb_b1, wq_w, wq_b, msg_w1, msg_b1, h_out);

    k2a_bn<<<128, 256>>>();
    k2b_bn<<<1, 64>>>(bn_g, bn_b);

    k3a_latent<<<NROWS / 128, 128, K3_SMEM>>>(eps, emb_w2, emb_b2, wk_w, wk_b);

    k4_msg<<<BSZ, 256>>>(msg_w1, msg_w2, msg_b2, ret_q);
}

// round 4
// speedup vs baseline: 2.6740x; 1.1016x over previous
#include <cuda_runtime.h>

#define NROWS 32768
#define BSZ   1024
#define AGN   32
#define IND   96
#define HDIM  64
#define NNHD  64
#define ATTD  32
#define NACTD 16
#define LDIM  16
#define DLAT  512

typedef unsigned long long u64;

// ---------------- scratch (device globals) ----------------
__device__ float g_z1[NROWS * NNHD];
__device__ float g_q[NROWS * NACTD];
__device__ float g_query[NROWS * ATTD];
__device__ float g_m1h[NROWS * NNHD];
__device__ float g_lat[BSZ * AGN * AGN * LDIM];   // [b][j][i][l]
__device__ float g_alpha[BSZ * AGN * AGN];        // [b][j][i]
__device__ float g_bn_a[NNHD];
__device__ float g_bn_c[NNHD];
__device__ float g_p1[128 * NNHD];
__device__ float g_p2[128 * NNHD];

// ---------------- packed f32x2 helpers ----------------
__device__ __forceinline__ u64 pk2(float lo, float hi) {
    u64 r; asm("mov.b64 %0, {%1, %2};" : "=l"(r) : "f"(lo), "f"(hi)); return r;
}
__device__ __forceinline__ void upk2(float& lo, float& hi, u64 v) {
    asm("mov.b64 {%0, %1}, %2;" : "=f"(lo), "=f"(hi) : "l"(v));
}
__device__ __forceinline__ u64 fma2_(u64 a, u64 b, u64 c) {
    u64 d; asm("fma.rn.f32x2 %0, %1, %2, %3;" : "=l"(d) : "l"(a), "l"(b), "l"(c)); return d;
}
__device__ __forceinline__ float red4(u64 a0, u64 a1, u64 a2, u64 a3) {
    float r0,r1,r2,r3,r4,r5,r6,r7;
    upk2(r0,r1,a0); upk2(r2,r3,a1); upk2(r4,r5,a2); upk2(r6,r7,a3);
    return ((r0+r1)+(r2+r3))+((r4+r5)+(r6+r7));
}

// dot: weights in smem loaded straight as packed u64 pairs (no MOV repack), z in regs
__device__ __forceinline__ float dot64s(const float* w, const u64 (&z)[32]) {
    const ulonglong2* w2 = reinterpret_cast<const ulonglong2*>(w);
    u64 a0=0ull, a1=0ull, a2=0ull, a3=0ull;
#pragma unroll
    for (int k = 0; k < 8; k++) {
        ulonglong2 u = w2[2*k], v = w2[2*k+1];
        a0 = fma2_(u.x, z[4*k+0], a0);
        a1 = fma2_(u.y, z[4*k+1], a1);
        a2 = fma2_(v.x, z[4*k+2], a2);
        a3 = fma2_(v.y, z[4*k+3], a3);
    }
    return red4(a0,a1,a2,a3);
}
__device__ __forceinline__ float dot96s(const float* w, const u64 (&z)[48]) {
    const ulonglong2* w2 = reinterpret_cast<const ulonglong2*>(w);
    u64 a0=0ull, a1=0ull, a2=0ull, a3=0ull;
#pragma unroll
    for (int k = 0; k < 12; k++) {
        ulonglong2 u = w2[2*k], v = w2[2*k+1];
        a0 = fma2_(u.x, z[4*k+0], a0);
        a1 = fma2_(u.y, z[4*k+1], a1);
        a2 = fma2_(v.x, z[4*k+2], a2);
        a3 = fma2_(v.y, z[4*k+3], a3);
    }
    return red4(a0,a1,a2,a3);
}
// dot: weights AND operand both in smem (packed loads on both)
__device__ __forceinline__ float dot64xs(const float* w, const float* x) {
    const ulonglong2* w2 = reinterpret_cast<const ulonglong2*>(w);
    const ulonglong2* x2 = reinterpret_cast<const ulonglong2*>(x);
    u64 a0=0ull, a1=0ull, a2=0ull, a3=0ull;
#pragma unroll
    for (int k = 0; k < 8; k++) {
        ulonglong2 u = w2[2*k], v = w2[2*k+1];
        ulonglong2 zu = x2[2*k], zv = x2[2*k+1];
        a0 = fma2_(u.x, zu.x, a0);
        a1 = fma2_(u.y, zu.y, a1);
        a2 = fma2_(v.x, zv.x, a2);
        a3 = fma2_(v.y, zv.y, a3);
    }
    return red4(a0,a1,a2,a3);
}

__device__ __forceinline__ void cload(float* dst, const float* __restrict__ src,
                                      int n4, int tid, int nthr) {
    float4* d = reinterpret_cast<float4*>(dst);
    const float4* s = reinterpret_cast<const float4*>(src);
    for (int i = tid; i < n4; i += nthr) d[i] = __ldg(s + i);
}

__device__ __forceinline__ float sigmoidf_(float x) { return 1.f / (1.f + expf(-x)); }

#define XSTR 68   // smem row stride (floats): 272B = 16B-aligned, conflict-free LDS.128

// ---------------- K1: fused trunk, 2 threads per row (p = output split) ----------------
__global__ void __launch_bounds__(256) k1_trunk(
    const float* __restrict__ inp, const float* __restrict__ h0,
    const float* __restrict__ fc1_w, const float* __restrict__ fc1_b,
    const float* __restrict__ wih, const float* __restrict__ whh,
    const float* __restrict__ bih, const float* __restrict__ bhh,
    const float* __restrict__ fc2_w, const float* __restrict__ fc2_b,
    const float* __restrict__ emb_w1, const float* __restrict__ emb_b1,
    const float* __restrict__ wq_w, const float* __restrict__ wq_b,
    const float* __restrict__ msg_w1, const float* __restrict__ msg_b1,
    float* __restrict__ h_out)
{
    extern __shared__ float sm1[];
    float* sX  = sm1;                     // 128*XSTR
    float* sH  = sm1 + 128 * XSTR;        // 128*XSTR
    float* wb0 = sm1 + 2 * 128 * XSTR;    // 3072
    float* wb1 = wb0 + 3072;              // 3072
    const int tid = threadIdx.x;
    const int p = tid >> 7;               // warp-uniform output-half
    const int r = tid & 127;
    const int row = blockIdx.x * 128 + r;
    float* myX = sX + r * XSTR;
    float* myH = sH + r * XSTR;

    // input row packed (both p threads)
    u64 xinp[48];
    {
        const float4* ip = reinterpret_cast<const float4*>(inp + (size_t)row * IND);
#pragma unroll
        for (int k = 0; k < 24; k++) {
            float4 v = __ldg(ip + k);
            xinp[2*k] = pk2(v.x, v.y); xinp[2*k+1] = pk2(v.z, v.w);
        }
    }
    // h0 -> smem (p==0 only)
    if (p == 0) {
        const float4* hp = reinterpret_cast<const float4*>(h0 + (size_t)row * HDIM);
#pragma unroll
        for (int k = 0; k < 16; k++) {
            float4 v = __ldg(hp + k);
            myH[4*k] = v.x; myH[4*k+1] = v.y; myH[4*k+2] = v.z; myH[4*k+3] = v.w;
        }
    }

    // ---- fc1: 2 chunks of 32 rows; each thread does 16 outputs per chunk ----
    cload(wb0, fc1_w, 768, tid, 256);
    __syncthreads();
    {   // chunk0 (o 0..31), prefetch chunk1
        cload(wb1, fc1_w + 3072, 768, tid, 256);
        for (int oo = 0; oo < 16; oo++) {
            int o = p * 16 + oo;
            myX[o] = fmaxf(__ldg(fc1_b + o) + dot96s(wb0 + o * 96, xinp), 0.f);
        }
        __syncthreads();
    }
    {   // chunk1 (o 32..63), prefetch GRU g=0
        {
            cload(wb0 + 0*512, wih,            128, tid, 256);
            cload(wb0 + 1*512, wih + 64*64,    128, tid, 256);
            cload(wb0 + 2*512, wih + 128*64,   128, tid, 256);
            cload(wb0 + 3*512, whh,            128, tid, 256);
            cload(wb0 + 4*512, whh + 64*64,    128, tid, 256);
            cload(wb0 + 5*512, whh + 128*64,   128, tid, 256);
        }
        for (int oo = 0; oo < 16; oo++) {
            int o = 32 + p * 16 + oo;
            myX[o] = fmaxf(__ldg(fc1_b + o) + dot96s(wb1 + (o - 32) * 96, xinp), 0.f);
        }
        __syncthreads();
    }

    // h packed regs (old h snapshot for all GRU dots)
    u64 hrp[32];
    {
        const ulonglong2* h2 = reinterpret_cast<const ulonglong2*>(myH);
#pragma unroll
        for (int k = 0; k < 16; k++) { ulonglong2 v = h2[k]; hrp[2*k] = v.x; hrp[2*k+1] = v.y; }
    }

    // ---- GRU: 8 chunks of 8 outputs; each thread does 4 ----
    for (int g = 0; g < 8; g++) {
        float* w  = (g & 1) ? wb1 : wb0;
        float* nx = (g & 1) ? wb0 : wb1;
        if (g < 7) {
            int o0 = (g + 1) * 8;
            cload(nx + 0*512, wih + (o0)*64,       128, tid, 256);
            cload(nx + 1*512, wih + (64+o0)*64,    128, tid, 256);
            cload(nx + 2*512, wih + (128+o0)*64,   128, tid, 256);
            cload(nx + 3*512, whh + (o0)*64,       128, tid, 256);
            cload(nx + 4*512, whh + (64+o0)*64,    128, tid, 256);
            cload(nx + 5*512, whh + (128+o0)*64,   128, tid, 256);
        } else {
            cload(nx, fc2_w, 256, tid, 256);
        }
        for (int q = 0; q < 4; q++) {
            int oo = p * 4 + q;
            int o = g * 8 + oo;
            float ar = __ldg(bih + o) + __ldg(bhh + o)
                     + dot64xs(w + oo*64,        myX) + dot64s(w + 1536 + oo*64, hrp);
            float az = __ldg(bih + 64 + o) + __ldg(bhh + 64 + o)
                     + dot64xs(w + 512 + oo*64,  myX) + dot64s(w + 2048 + oo*64, hrp);
            float ai = __ldg(bih + 128 + o) + dot64xs(w + 1024 + oo*64, myX);
            float ah = __ldg(bhh + 128 + o) + dot64s(w + 2560 + oo*64, hrp);
            float rr = sigmoidf_(ar);
            float zz = sigmoidf_(az);
            float nn = tanhf(ai + rr * ah);
            myH[o] = (1.f - zz) * nn + zz * myH[o];
        }
        __syncthreads();
    }
    // rebuild packed new h
    {
        const ulonglong2* h2 = reinterpret_cast<const ulonglong2*>(myH);
#pragma unroll
        for (int k = 0; k < 16; k++) { ulonglong2 v = h2[k]; hrp[2*k] = v.x; hrp[2*k+1] = v.y; }
    }
    // h out (split halves)
    {
        float4* hop = reinterpret_cast<float4*>(h_out + (size_t)row * HDIM);
#pragma unroll
        for (int k = 0; k < 8; k++) {
            int kk = p * 8 + k;
            hop[kk] = make_float4(myH[4*kk], myH[4*kk+1], myH[4*kk+2], myH[4*kk+3]);
        }
    }

    // ---- heads (fc2 already in wb0) ----
    {   // q (16): each p does 8; prefetch emb_w1 rows 0..31
        cload(wb1, emb_w1, 512, tid, 256);
        float4* dst = reinterpret_cast<float4*>(g_q + (size_t)row * NACTD);
        for (int o4 = 2*p; o4 < 2*p + 2; o4++) {
            float v0 = __ldg(fc2_b + 4*o4+0) + dot64s(wb0 + (4*o4+0)*64, hrp);
            float v1 = __ldg(fc2_b + 4*o4+1) + dot64s(wb0 + (4*o4+1)*64, hrp);
            float v2 = __ldg(fc2_b + 4*o4+2) + dot64s(wb0 + (4*o4+2)*64, hrp);
            float v3 = __ldg(fc2_b + 4*o4+3) + dot64s(wb0 + (4*o4+3)*64, hrp);
            dst[o4] = make_float4(v0, v1, v2, v3);
        }
        __syncthreads();
    }
    {   // z1 rows 0..31; prefetch emb_w1 rows 32..63
        cload(wb0, emb_w1 + 2048, 512, tid, 256);
        float4* dst = reinterpret_cast<float4*>(g_z1 + (size_t)row * NNHD);
        for (int o4 = 4*p; o4 < 4*p + 4; o4++) {
            float v0 = __ldg(emb_b1 + 4*o4+0) + dot64s(wb1 + (4*o4+0)*64, hrp);
            float v1 = __ldg(emb_b1 + 4*o4+1) + dot64s(wb1 + (4*o4+1)*64, hrp);
            float v2 = __ldg(emb_b1 + 4*o4+2) + dot64s(wb1 + (4*o4+2)*64, hrp);
            float v3 = __ldg(emb_b1 + 4*o4+3) + dot64s(wb1 + (4*o4+3)*64, hrp);
            dst[o4] = make_float4(v0, v1, v2, v3);
        }
        __syncthreads();
    }
    {   // z1 rows 32..63; prefetch wq
        cload(wb1, wq_w, 512, tid, 256);
        float4* dst = reinterpret_cast<float4*>(g_z1 + (size_t)row * NNHD) + 8;
        for (int o4 = 4*p; o4 < 4*p + 4; o4++) {
            float v0 = __ldg(emb_b1 + 32 + 4*o4+0) + dot64s(wb0 + (4*o4+0)*64, hrp);
            float v1 = __ldg(emb_b1 + 32 + 4*o4+1) + dot64s(wb0 + (4*o4+1)*64, hrp);
            float v2 = __ldg(emb_b1 + 32 + 4*o4+2) + dot64s(wb0 + (4*o4+2)*64, hrp);
            float v3 = __ldg(emb_b1 + 32 + 4*o4+3) + dot64s(wb0 + (4*o4+3)*64, hrp);
            dst[o4] = make_float4(v0, v1, v2, v3);
        }
        __syncthreads();
    }
    {   // query (scaled); prefetch msg_w1 rows 0..31 (80-wide)
        cload(wb0, msg_w1, 640, tid, 256);
        const float qs = 0.17677669529663687f;
        float4* dst = reinterpret_cast<float4*>(g_query + (size_t)row * ATTD);
        for (int o4 = 4*p; o4 < 4*p + 4; o4++) {
            float v0 = (__ldg(wq_b + 4*o4+0) + dot64s(wb1 + (4*o4+0)*64, hrp)) * qs;
            float v1 = (__ldg(wq_b + 4*o4+1) + dot64s(wb1 + (4*o4+1)*64, hrp)) * qs;
            float v2 = (__ldg(wq_b + 4*o4+2) + dot64s(wb1 + (4*o4+2)*64, hrp)) * qs;
            float v3 = (__ldg(wq_b + 4*o4+3) + dot64s(wb1 + (4*o4+3)*64, hrp)) * qs;
            dst[o4] = make_float4(v0, v1, v2, v3);
        }
        __syncthreads();
    }
    {   // m1h rows 0..31; prefetch msg_w1 rows 32..63
        cload(wb1, msg_w1 + 2560, 640, tid, 256);
        float4* dst = reinterpret_cast<float4*>(g_m1h + (size_t)row * NNHD);
        for (int o4 = 4*p; o4 < 4*p + 4; o4++) {
            float v0 = __ldg(msg_b1 + 4*o4+0) + dot64s(wb0 + (4*o4+0)*80, hrp);
            float v1 = __ldg(msg_b1 + 4*o4+1) + dot64s(wb0 + (4*o4+1)*80, hrp);
            float v2 = __ldg(msg_b1 + 4*o4+2) + dot64s(wb0 + (4*o4+2)*80, hrp);
            float v3 = __ldg(msg_b1 + 4*o4+3) + dot64s(wb0 + (4*o4+3)*80, hrp);
            dst[o4] = make_float4(v0, v1, v2, v3);
        }
        __syncthreads();
    }
    {   // m1h rows 32..63
        float4* dst = reinterpret_cast<float4*>(g_m1h + (size_t)row * NNHD) + 8;
        for (int o4 = 4*p; o4 < 4*p + 4; o4++) {
            float v0 = __ldg(msg_b1 + 32 + 4*o4+0) + dot64s(wb1 + (4*o4+0)*80, hrp);
            float v1 = __ldg(msg_b1 + 32 + 4*o4+1) + dot64s(wb1 + (4*o4+1)*80, hrp);
            float v2 = __ldg(msg_b1 + 32 + 4*o4+2) + dot64s(wb1 + (4*o4+2)*80, hrp);
            float v3 = __ldg(msg_b1 + 32 + 4*o4+3) + dot64s(wb1 + (4*o4+3)*80, hrp);
            dst[o4] = make_float4(v0, v1, v2, v3);
        }
    }
}

// ---------------- K2a/K2b: BN statistics ----------------
__global__ void __launch_bounds__(256) k2a_bn()
{
    __shared__ float ss[4][NNHD], sq[4][NNHD];
    const int tid = threadIdx.x;
    const int f = tid & 63;
    const int rg = tid >> 6;
    const int base = blockIdx.x * 256;
    float s = 0.f, q = 0.f;
    for (int r = rg; r < 256; r += 4) {
        float v = g_z1[(size_t)(base + r) * NNHD + f];
        s += v; q += v * v;
    }
    ss[rg][f] = s; sq[rg][f] = q;
    __syncthreads();
    if (tid < NNHD) {
        g_p1[blockIdx.x * NNHD + tid] = ss[0][tid] + ss[1][tid] + ss[2][tid] + ss[3][tid];
        g_p2[blockIdx.x * NNHD + tid] = sq[0][tid] + sq[1][tid] + sq[2][tid] + sq[3][tid];
    }
}
__global__ void __launch_bounds__(64) k2b_bn(const float* __restrict__ bn_g,
                                            const float* __restrict__ bn_b)
{
    const int f = threadIdx.x;
    float s = 0.f, q = 0.f;
    for (int i = 0; i < 128; i++) { s += g_p1[i * NNHD + f]; q += g_p2[i * NNHD + f]; }
    float mean = s * (1.f / (float)NROWS);
    float var  = q * (1.f / (float)NROWS) - mean * mean;
    float a = __ldg(bn_g + f) / sqrtf(var + 1e-5f);
    g_bn_a[f] = a;
    g_bn_c[f] = __ldg(bn_b + f) - a * mean;
}

// ---------------- K3a: latent GEMM + fused alpha + softmax (2 threads per row) ----------------
__global__ void __launch_bounds__(256) k3a_latent(
    const float* __restrict__ eps,
    const float* __restrict__ emb_w2, const float* __restrict__ emb_b2,
    const float* __restrict__ wk_w, const float* __restrict__ wk_b)
{
    extern __shared__ float sm3[];
    float* wbuf0 = sm3;            // 4096: [0..2047]=mu rows, [2048..4095]=lg rows
    float* wbuf1 = sm3 + 4096;
    float* swk   = sm3 + 8192;     // 512
    float* sAl   = sm3 + 8704;     // 128*33
    const int tid = threadIdx.x;
    const int p = tid >> 7;        // warp-uniform d-half
    const int r = tid & 127;
    const int row = blockIdx.x * 128 + r;
    const int b = row >> 5;
    const int i = row & 31;

    // z1 -> BN affine -> lrelu -> packed regs (both p threads)
    u64 zp[32];
    {
        const float4* zpg = reinterpret_cast<const float4*>(g_z1 + (size_t)row * NNHD);
#pragma unroll
        for (int k = 0; k < 16; k++) {
            float4 v = __ldg(zpg + k);
            float t0 = g_bn_a[4*k+0] * v.x + g_bn_c[4*k+0]; t0 = t0 > 0.f ? t0 : 0.01f * t0;
            float t1 = g_bn_a[4*k+1] * v.y + g_bn_c[4*k+1]; t1 = t1 > 0.f ? t1 : 0.01f * t1;
            float t2 = g_bn_a[4*k+2] * v.z + g_bn_c[4*k+2]; t2 = t2 > 0.f ? t2 : 0.01f * t2;
            float t3 = g_bn_a[4*k+3] * v.w + g_bn_c[4*k+3]; t3 = t3 > 0.f ? t3 : 0.01f * t3;
            zp[2*k] = pk2(t0, t1); zp[2*k+1] = pk2(t2, t3);
        }
    }

    cload(wbuf0,        emb_w2,            512, tid, 256);
    cload(wbuf0 + 2048, emb_w2 + 512 * 64, 512, tid, 256);
    cload(swk, wk_w, 128, tid, 256);
    __syncthreads();

    // folded query: qk[l] = sum_a q[a]*wk[a][l];  qb = q . wk_b
    float qk[16];
#pragma unroll
    for (int l = 0; l < 16; l++) qk[l] = 0.f;
    float qb = 0.f;
    {
        const float4* qp = reinterpret_cast<const float4*>(g_query + (size_t)row * ATTD);
#pragma unroll
        for (int k = 0; k < 8; k++) {
            float4 v = __ldg(qp + k);
            float qa[4] = {v.x, v.y, v.z, v.w};
#pragma unroll
            for (int u = 0; u < 4; u++) {
                int a = 4*k + u;
#pragma unroll
                for (int l = 0; l < 16; l++) qk[l] = fmaf(qa[u], swk[a*16 + l], qk[l]);
                qb = fmaf(qa[u], __ldg(wk_b + a), qb);
            }
        }
    }

    float* myAl = sAl + r * 33;
    const float* epsrow = eps + (size_t)row * DLAT;

    for (int c = 0; c < 16; c++) {
        float* w = (c & 1) ? wbuf1 : wbuf0;
        if (c < 15) {
            float* nw = (c & 1) ? wbuf0 : wbuf1;
            int d0n = (c + 1) * 32;
            cload(nw,        emb_w2 + d0n * 64,         512, tid, 256);
            cload(nw + 2048, emb_w2 + (512 + d0n) * 64, 512, tid, 256);
        }
        const int j = 2 * c + p;                 // this thread's j
        const int dbase = c * 32 + 16 * p;       // global d start (16 values)
        float acc = qb;
        float* latdst = g_lat + ((size_t)((b * AGN + j) * AGN + i)) * LDIM;
#pragma unroll
        for (int g = 0; g < 4; g++) {
            float4 e4 = __ldg(reinterpret_cast<const float4*>(epsrow + dbase + 4*g));
            float ev[4] = {e4.x, e4.y, e4.z, e4.w};
            float lat[4];
#pragma unroll
            for (int u = 0; u < 4; u++) {
                int dg = 16*p + 4*g + u;         // index within chunk buffer
                int d  = dbase + 4*g + u;        // global d
                float mu = __ldg(emb_b2 + d) + dot64s(w + dg * 64, zp);
                float lg = __ldg(emb_b2 + 512 + d) + dot64s(w + 2048 + dg * 64, zp);
                lat[u] = mu + sqrtf(fmaxf(expf(lg), 0.002f)) * ev[u];
                acc = fmaf(qk[4*g + u], lat[u], acc);
            }
            *reinterpret_cast<float4*>(latdst + 4*g) = make_float4(lat[0], lat[1], lat[2], lat[3]);
        }
        myAl[j] = acc;
        __syncthreads();
    }

    // masked softmax over j (p==0 half only; final loop sync covers partner writes)
    if (p == 0) {
        myAl[i] = -1e9f;
        float m = -3.4e38f;
        for (int j = 0; j < AGN; j++) m = fmaxf(m, myAl[j]);
        float ssum = 0.f;
        for (int j = 0; j < AGN; j++) { float e = expf(myAl[j] - m); myAl[j] = e; ssum += e; }
        float inv = 1.f / ssum;
        for (int j = 0; j < AGN; j++)
            g_alpha[(size_t)(b * AGN + j) * AGN + i] = myAl[j] * inv;
    }
}

// ---------------- K4: message MLP + weighted aggregate + q add ----------------
__global__ void __launch_bounds__(256) k4_msg(
    const float* __restrict__ msg_w1,
    const float* __restrict__ msg_w2, const float* __restrict__ msg_b2,
    float* __restrict__ ret_q)
{
    __shared__ float sW2[16 * 68];
    __shared__ float sB2[16];
    __shared__ float sU[8][68];
    const int tid = threadIdx.x;
    const int w = tid >> 5;
    const int lane = tid & 31;
    const int b = blockIdx.x;

    for (int idx = tid; idx < 16 * 64; idx += 256) {
        int rr = idx >> 6, cc = idx & 63;
        sW2[rr * 68 + cc] = __ldg(msg_w2 + idx);
    }
    if (tid < 16) sB2[tid] = __ldg(msg_b2 + tid);

    u64 w1a[8], w1b[8];
    {
        const float4* p0 = reinterpret_cast<const float4*>(msg_w1 + lane * 80 + 64);
        const float4* p1 = reinterpret_cast<const float4*>(msg_w1 + (lane + 32) * 80 + 64);
#pragma unroll
        for (int k = 0; k < 4; k++) {
            float4 v0 = __ldg(p0 + k), v1 = __ldg(p1 + k);
            w1a[2*k] = pk2(v0.x, v0.y); w1a[2*k+1] = pk2(v0.z, v0.w);
            w1b[2*k] = pk2(v1.x, v1.y); w1b[2*k+1] = pk2(v1.z, v1.w);
        }
    }
    __syncthreads();

#pragma unroll
    for (int jj = 0; jj < 4; jj++) {
        const int j = w + jj * 8;
        const int bj = b * AGN + j;
        const float m0 = __ldg(g_m1h + (size_t)bj * NNHD + lane);
        const float m1 = __ldg(g_m1h + (size_t)bj * NNHD + 32 + lane);
        const float* latbase = g_lat + (size_t)bj * AGN * LDIM;
        const float* alb = g_alpha + (size_t)bj * AGN;
        float u0 = 0.f, u1 = 0.f, sa = 0.f;

        for (int i = 0; i < AGN; i++) {
            const float4* l4 = reinterpret_cast<const float4*>(latbase + i * LDIM);
            float4 A = __ldg(l4), B = __ldg(l4+1), C = __ldg(l4+2), D = __ldg(l4+3);
            u64 z0 = pk2(A.x,A.y), z1 = pk2(A.z,A.w), z2 = pk2(B.x,B.y), z3 = pk2(B.z,B.w);
            u64 z4 = pk2(C.x,C.y), z5 = pk2(C.z,C.w), z6 = pk2(D.x,D.y), z7 = pk2(D.z,D.w);
            u64 a0 = 0ull, a1 = 0ull, b0 = 0ull, b1 = 0ull;
            a0 = fma2_(w1a[0], z0, a0); a1 = fma2_(w1a[1], z1, a1);
            b0 = fma2_(w1b[0], z0, b0); b1 = fma2_(w1b[1], z1, b1);
            a0 = fma2_(w1a[2], z2, a0); a1 = fma2_(w1a[3], z3, a1);
            b0 = fma2_(w1b[2], z2, b0); b1 = fma2_(w1b[3], z3, b1);
            a0 = fma2_(w1a[4], z4, a0); a1 = fma2_(w1a[5], z5, a1);
            b0 = fma2_(w1b[4], z4, b0); b1 = fma2_(w1b[5], z5, b1);
            a0 = fma2_(w1a[6], z6, a0); a1 = fma2_(w1a[7], z7, a1);
            b0 = fma2_(w1b[6], z6, b0); b1 = fma2_(w1b[7], z7, b1);
            float r0,r1,r2,r3; upk2(r0,r1,a0); upk2(r2,r3,a1);
            float s0 = m0 + ((r0+r1)+(r2+r3));
            upk2(r0,r1,b0); upk2(r2,r3,b1);
            float s1 = m1 + ((r0+r1)+(r2+r3));
            s0 = s0 > 0.f ? s0 : 0.01f * s0;
            s1 = s1 > 0.f ? s1 : 0.01f * s1;
            float al = __ldg(alb + i);
            sa += al;
            u0 = fmaf(al, s0, u0);
            u1 = fmaf(al, s1, u1);
        }
        sU[w][lane] = u0; sU[w][32 + lane] = u1;
        __syncwarp();
        if (lane < 16) {
            float acc = __ldg(g_q + (size_t)bj * NACTD + lane) + sa * sB2[lane];
            const float* w2r = sW2 + lane * 68;
            const float* uv = sU[w];
            float c0 = 0.f, c1 = 0.f;
#pragma unroll
            for (int o = 0; o < 64; o += 2) {
                c0 = fmaf(w2r[o],   uv[o],   c0);
                c1 = fmaf(w2r[o+1], uv[o+1], c1);
            }
            ret_q[(size_t)bj * NACTD + lane] = acc + c0 + c1;
        }
        __syncwarp();
    }
}

// ---------------- host launcher ----------------
extern "C" void kernel_launch(void* const* d_in, const int* in_sizes, int n_in,
                              void* d_out, int out_size)
{
    (void)in_sizes; (void)n_in; (void)out_size;
    const float* inputs  = (const float*)d_in[0];
    const float* hidden  = (const float*)d_in[1];
    const float* eps     = (const float*)d_in[2];
    const float* fc1_w   = (const float*)d_in[3];
    const float* fc1_b   = (const float*)d_in[4];
    const float* gru_wih = (const float*)d_in[5];
    const float* gru_whh = (const float*)d_in[6];
    const float* gru_bih = (const float*)d_in[7];
    const float* gru_bhh = (const float*)d_in[8];
    const float* fc2_w   = (const float*)d_in[9];
    const float* fc2_b   = (const float*)d_in[10];
    const float* emb_w1  = (const float*)d_in[11];
    const float* emb_b1  = (const float*)d_in[12];
    const float* bn_g    = (const float*)d_in[13];
    const float* bn_b    = (const float*)d_in[14];
    const float* emb_w2  = (const float*)d_in[15];
    const float* emb_b2  = (const float*)d_in[16];
    const float* msg_w1  = (const float*)d_in[17];
    const float* msg_b1  = (const float*)d_in[18];
    const float* msg_w2  = (const float*)d_in[19];
    const float* msg_b2  = (const float*)d_in[20];
    const float* wq_w    = (const float*)d_in[21];
    const float* wq_b    = (const float*)d_in[22];
    const float* wk_w    = (const float*)d_in[23];
    const float* wk_b    = (const float*)d_in[24];

    float* out   = (float*)d_out;
    float* ret_q = out;                          // [32768,16]
    float* h_out = out + (size_t)NROWS * NACTD;  // [32768,64]

    const int K1_SMEM = (2 * 128 * XSTR + 2 * 3072) * sizeof(float);  // 94,208 B
    const int K3_SMEM = (2 * 4096 + 512 + 128 * 33) * sizeof(float);  // 51,712 B
    cudaFuncSetAttribute(k1_trunk,   cudaFuncAttributeMaxDynamicSharedMemorySize, K1_SMEM);
    cudaFuncSetAttribute(k3a_latent, cudaFuncAttributeMaxDynamicSharedMemorySize, K3_SMEM);

    k1_trunk<<<NROWS / 128, 256, K1_SMEM>>>(
        inputs, hidden, fc1_w, fc1_b, gru_wih, gru_whh, gru_bih, gru_bhh,
        fc2_w, fc2_b, emb_w1, emb_b1, wq_w, wq_b, msg_w1, msg_b1, h_out);

    k2a_bn<<<128, 256>>>();
    k2b_bn<<<1, 64>>>(bn_g, bn_b);

    k3a_latent<<<NROWS / 128, 256, K3_SMEM>>>(eps, emb_w2, emb_b2, wk_w, wk_b);

    k4_msg<<<BSZ, 256>>>(msg_w1, msg_w2, msg_b2, ret_q);
}

// round 6
// speedup vs baseline: 3.8191x; 1.4282x over previous
#include <cuda_runtime.h>
#include <cuda_bf16.h>
#include <cstdint>

#define NROWS 32768
#define BSZ   1024
#define AGN   32
#define IND   96
#define HDIM  64
#define NNHD  64
#define ATTD  32
#define NACTD 16
#define LDIM  16
#define DLAT  512

typedef unsigned long long u64;

// ---------------- scratch (device globals) ----------------
__device__ float g_z1[NROWS * NNHD];
__device__ float g_q[NROWS * NACTD];
__device__ float g_query[NROWS * ATTD];
__device__ float g_m1h[NROWS * NNHD];
__device__ float g_lat[BSZ * AGN * AGN * LDIM];   // [b][j][i][l]
__device__ float g_alpha[BSZ * AGN * AGN];        // RAW scores [b][j][i]
__device__ float g_bn_a[NNHD];
__device__ float g_bn_c[NNHD];
__device__ float g_p1[128 * NNHD];
__device__ float g_p2[128 * NNHD];

// ---------------- packed f32x2 helpers ----------------
__device__ __forceinline__ u64 pk2(float lo, float hi) {
    u64 r; asm("mov.b64 %0, {%1, %2};" : "=l"(r) : "f"(lo), "f"(hi)); return r;
}
__device__ __forceinline__ void upk2(float& lo, float& hi, u64 v) {
    asm("mov.b64 {%0, %1}, %2;" : "=f"(lo), "=f"(hi) : "l"(v));
}
__device__ __forceinline__ u64 fma2_(u64 a, u64 b, u64 c) {
    u64 d; asm("fma.rn.f32x2 %0, %1, %2, %3;" : "=l"(d) : "l"(a), "l"(b), "l"(c)); return d;
}
__device__ __forceinline__ float red4(u64 a0, u64 a1, u64 a2, u64 a3) {
    float r0,r1,r2,r3,r4,r5,r6,r7;
    upk2(r0,r1,a0); upk2(r2,r3,a1); upk2(r4,r5,a2); upk2(r6,r7,a3);
    return ((r0+r1)+(r2+r3))+((r4+r5)+(r6+r7));
}
__device__ __forceinline__ float dot64s(const float* w, const u64 (&z)[32]) {
    const ulonglong2* w2 = reinterpret_cast<const ulonglong2*>(w);
    u64 a0=0ull, a1=0ull, a2=0ull, a3=0ull;
#pragma unroll
    for (int k = 0; k < 8; k++) {
        ulonglong2 u = w2[2*k], v = w2[2*k+1];
        a0 = fma2_(u.x, z[4*k+0], a0);
        a1 = fma2_(u.y, z[4*k+1], a1);
        a2 = fma2_(v.x, z[4*k+2], a2);
        a3 = fma2_(v.y, z[4*k+3], a3);
    }
    return red4(a0,a1,a2,a3);
}
__device__ __forceinline__ float dot96s(const float* w, const u64 (&z)[48]) {
    const ulonglong2* w2 = reinterpret_cast<const ulonglong2*>(w);
    u64 a0=0ull, a1=0ull, a2=0ull, a3=0ull;
#pragma unroll
    for (int k = 0; k < 12; k++) {
        ulonglong2 u = w2[2*k], v = w2[2*k+1];
        a0 = fma2_(u.x, z[4*k+0], a0);
        a1 = fma2_(u.y, z[4*k+1], a1);
        a2 = fma2_(v.x, z[4*k+2], a2);
        a3 = fma2_(v.y, z[4*k+3], a3);
    }
    return red4(a0,a1,a2,a3);
}
__device__ __forceinline__ float dot64xs(const float* w, const float* x) {
    const ulonglong2* w2 = reinterpret_cast<const ulonglong2*>(w);
    const ulonglong2* x2 = reinterpret_cast<const ulonglong2*>(x);
    u64 a0=0ull, a1=0ull, a2=0ull, a3=0ull;
#pragma unroll
    for (int k = 0; k < 8; k++) {
        ulonglong2 u = w2[2*k], v = w2[2*k+1];
        ulonglong2 zu = x2[2*k], zv = x2[2*k+1];
        a0 = fma2_(u.x, zu.x, a0);
        a1 = fma2_(u.y, zu.y, a1);
        a2 = fma2_(v.x, zv.x, a2);
        a3 = fma2_(v.y, zv.y, a3);
    }
    return red4(a0,a1,a2,a3);
}
__device__ __forceinline__ void cload(float* dst, const float* __restrict__ src,
                                      int n4, int tid, int nthr) {
    float4* d = reinterpret_cast<float4*>(dst);
    const float4* s = reinterpret_cast<const float4*>(src);
    for (int i = tid; i < n4; i += nthr) d[i] = __ldg(s + i);
}
__device__ __forceinline__ float sigmoidf_(float x) {
    return __fdividef(1.f, 1.f + __expf(-x));
}

// ---------------- warp MMA plumbing (sm_80+ path, compiles for compute_103) ----------------
__device__ __forceinline__ uint32_t smem_u32(const void* p) {
    uint32_t a;
    asm("{ .reg .u64 t; cvta.to.shared.u64 t, %1; cvt.u32.u64 %0, t; }" : "=r"(a) : "l"(p));
    return a;
}
#define SWZ128(o) ((o) ^ (((o) >> 3) & 0x70))
__device__ __forceinline__ void ldsm_x4(uint32_t& r0, uint32_t& r1, uint32_t& r2, uint32_t& r3,
                                        uint32_t addr) {
    asm volatile("ldmatrix.sync.aligned.m8n8.x4.shared.b16 {%0,%1,%2,%3}, [%4];"
                 : "=r"(r0), "=r"(r1), "=r"(r2), "=r"(r3) : "r"(addr));
}
__device__ __forceinline__ void ldsm_x2(uint32_t& r0, uint32_t& r1, uint32_t addr) {
    asm volatile("ldmatrix.sync.aligned.m8n8.x2.shared.b16 {%0,%1}, [%2];"
                 : "=r"(r0), "=r"(r1) : "r"(addr));
}
__device__ __forceinline__ void mma16816(float* d, const uint32_t* a, uint32_t b0, uint32_t b1) {
    asm volatile(
        "mma.sync.aligned.m16n8k16.row.col.f32.bf16.bf16.f32 "
        "{%0,%1,%2,%3}, {%4,%5,%6,%7}, {%8,%9}, {%0,%1,%2,%3};"
        : "+f"(d[0]), "+f"(d[1]), "+f"(d[2]), "+f"(d[3])
        : "r"(a[0]), "r"(a[1]), "r"(a[2]), "r"(a[3]), "r"(b0), "r"(b1));
}
__device__ __forceinline__ void bf_split2(float a, float b, uint32_t& hi, uint32_t& lo) {
    __nv_bfloat16 ha = __float2bfloat16(a), hb = __float2bfloat16(b);
    float ra = a - __bfloat162float(ha);
    float rb = b - __bfloat162float(hb);
    __nv_bfloat162 H = __halves2bfloat162(ha, hb);
    __nv_bfloat162 L = __floats2bfloat162_rn(ra, rb);
    hi = *reinterpret_cast<uint32_t*>(&H);
    lo = *reinterpret_cast<uint32_t*>(&L);
}

// ---------------- K1: fused trunk (R4) ----------------
#define XSTR 68
__global__ void __launch_bounds__(256) k1_trunk(
    const float* __restrict__ inp, const float* __restrict__ h0,
    const float* __restrict__ fc1_w, const float* __restrict__ fc1_b,
    const float* __restrict__ wih, const float* __restrict__ whh,
    const float* __restrict__ bih, const float* __restrict__ bhh,
    const float* __restrict__ fc2_w, const float* __restrict__ fc2_b,
    const float* __restrict__ emb_w1, const float* __restrict__ emb_b1,
    const float* __restrict__ wq_w, const float* __restrict__ wq_b,
    const float* __restrict__ msg_w1, const float* __restrict__ msg_b1,
    float* __restrict__ h_out)
{
    extern __shared__ float sm1[];
    float* sX  = sm1;
    float* sH  = sm1 + 128 * XSTR;
    float* wb0 = sm1 + 2 * 128 * XSTR;
    float* wb1 = wb0 + 3072;
    const int tid = threadIdx.x;
    const int p = tid >> 7;
    const int r = tid & 127;
    const int row = blockIdx.x * 128 + r;
    float* myX = sX + r * XSTR;
    float* myH = sH + r * XSTR;

    u64 xinp[48];
    {
        const float4* ip = reinterpret_cast<const float4*>(inp + (size_t)row * IND);
#pragma unroll
        for (int k = 0; k < 24; k++) {
            float4 v = __ldg(ip + k);
            xinp[2*k] = pk2(v.x, v.y); xinp[2*k+1] = pk2(v.z, v.w);
        }
    }
    if (p == 0) {
        const float4* hp = reinterpret_cast<const float4*>(h0 + (size_t)row * HDIM);
#pragma unroll
        for (int k = 0; k < 16; k++) {
            float4 v = __ldg(hp + k);
            myH[4*k] = v.x; myH[4*k+1] = v.y; myH[4*k+2] = v.z; myH[4*k+3] = v.w;
        }
    }

    cload(wb0, fc1_w, 768, tid, 256);
    __syncthreads();
    {
        cload(wb1, fc1_w + 3072, 768, tid, 256);
        for (int oo = 0; oo < 16; oo++) {
            int o = p * 16 + oo;
            myX[o] = fmaxf(__ldg(fc1_b + o) + dot96s(wb0 + o * 96, xinp), 0.f);
        }
        __syncthreads();
    }
    {
        cload(wb0 + 0*512, wih,            128, tid, 256);
        cload(wb0 + 1*512, wih + 64*64,    128, tid, 256);
        cload(wb0 + 2*512, wih + 128*64,   128, tid, 256);
        cload(wb0 + 3*512, whh,            128, tid, 256);
        cload(wb0 + 4*512, whh + 64*64,    128, tid, 256);
        cload(wb0 + 5*512, whh + 128*64,   128, tid, 256);
        for (int oo = 0; oo < 16; oo++) {
            int o = 32 + p * 16 + oo;
            myX[o] = fmaxf(__ldg(fc1_b + o) + dot96s(wb1 + (o - 32) * 96, xinp), 0.f);
        }
        __syncthreads();
    }

    u64 hrp[32];
    {
        const ulonglong2* h2 = reinterpret_cast<const ulonglong2*>(myH);
#pragma unroll
        for (int k = 0; k < 16; k++) { ulonglong2 v = h2[k]; hrp[2*k] = v.x; hrp[2*k+1] = v.y; }
    }

    for (int g = 0; g < 8; g++) {
        float* w  = (g & 1) ? wb1 : wb0;
        float* nx = (g & 1) ? wb0 : wb1;
        if (g < 7) {
            int o0 = (g + 1) * 8;
            cload(nx + 0*512, wih + (o0)*64,       128, tid, 256);
            cload(nx + 1*512, wih + (64+o0)*64,    128, tid, 256);
            cload(nx + 2*512, wih + (128+o0)*64,   128, tid, 256);
            cload(nx + 3*512, whh + (o0)*64,       128, tid, 256);
            cload(nx + 4*512, whh + (64+o0)*64,    128, tid, 256);
            cload(nx + 5*512, whh + (128+o0)*64,   128, tid, 256);
        } else {
            cload(nx, fc2_w, 256, tid, 256);
        }
        for (int q = 0; q < 4; q++) {
            int oo = p * 4 + q;
            int o = g * 8 + oo;
            float ar = __ldg(bih + o) + __ldg(bhh + o)
                     + dot64xs(w + oo*64,        myX) + dot64s(w + 1536 + oo*64, hrp);
            float az = __ldg(bih + 64 + o) + __ldg(bhh + 64 + o)
                     + dot64xs(w + 512 + oo*64,  myX) + dot64s(w + 2048 + oo*64, hrp);
            float ai = __ldg(bih + 128 + o) + dot64xs(w + 1024 + oo*64, myX);
            float ah = __ldg(bhh + 128 + o) + dot64s(w + 2560 + oo*64, hrp);
            float rr = sigmoidf_(ar);
            float zz = sigmoidf_(az);
            float nn = tanhf(ai + rr * ah);
            myH[o] = (1.f - zz) * nn + zz * myH[o];
        }
        __syncthreads();
    }
    {
        const ulonglong2* h2 = reinterpret_cast<const ulonglong2*>(myH);
#pragma unroll
        for (int k = 0; k < 16; k++) { ulonglong2 v = h2[k]; hrp[2*k] = v.x; hrp[2*k+1] = v.y; }
    }
    {
        float4* hop = reinterpret_cast<float4*>(h_out + (size_t)row * HDIM);
#pragma unroll
        for (int k = 0; k < 8; k++) {
            int kk = p * 8 + k;
            hop[kk] = make_float4(myH[4*kk], myH[4*kk+1], myH[4*kk+2], myH[4*kk+3]);
        }
    }
    {
        cload(wb1, emb_w1, 512, tid, 256);
        float4* dst = reinterpret_cast<float4*>(g_q + (size_t)row * NACTD);
        for (int o4 = 2*p; o4 < 2*p + 2; o4++) {
            float v0 = __ldg(fc2_b + 4*o4+0) + dot64s(wb0 + (4*o4+0)*64, hrp);
            float v1 = __ldg(fc2_b + 4*o4+1) + dot64s(wb0 + (4*o4+1)*64, hrp);
            float v2 = __ldg(fc2_b + 4*o4+2) + dot64s(wb0 + (4*o4+2)*64, hrp);
            float v3 = __ldg(fc2_b + 4*o4+3) + dot64s(wb0 + (4*o4+3)*64, hrp);
            dst[o4] = make_float4(v0, v1, v2, v3);
        }
        __syncthreads();
    }
    {
        cload(wb0, emb_w1 + 2048, 512, tid, 256);
        float4* dst = reinterpret_cast<float4*>(g_z1 + (size_t)row * NNHD);
        for (int o4 = 4*p; o4 < 4*p + 4; o4++) {
            float v0 = __ldg(emb_b1 + 4*o4+0) + dot64s(wb1 + (4*o4+0)*64, hrp);
            float v1 = __ldg(emb_b1 + 4*o4+1) + dot64s(wb1 + (4*o4+1)*64, hrp);
            float v2 = __ldg(emb_b1 + 4*o4+2) + dot64s(wb1 + (4*o4+2)*64, hrp);
            float v3 = __ldg(emb_b1 + 4*o4+3) + dot64s(wb1 + (4*o4+3)*64, hrp);
            dst[o4] = make_float4(v0, v1, v2, v3);
        }
        __syncthreads();
    }
    {
        cload(wb1, wq_w, 512, tid, 256);
        float4* dst = reinterpret_cast<float4*>(g_z1 + (size_t)row * NNHD) + 8;
        for (int o4 = 4*p; o4 < 4*p + 4; o4++) {
            float v0 = __ldg(emb_b1 + 32 + 4*o4+0) + dot64s(wb0 + (4*o4+0)*64, hrp);
            float v1 = __ldg(emb_b1 + 32 + 4*o4+1) + dot64s(wb0 + (4*o4+1)*64, hrp);
            float v2 = __ldg(emb_b1 + 32 + 4*o4+2) + dot64s(wb0 + (4*o4+2)*64, hrp);
            float v3 = __ldg(emb_b1 + 32 + 4*o4+3) + dot64s(wb0 + (4*o4+3)*64, hrp);
            dst[o4] = make_float4(v0, v1, v2, v3);
        }
        __syncthreads();
    }
    {
        cload(wb0, msg_w1, 640, tid, 256);
        const float qs = 0.17677669529663687f;
        float4* dst = reinterpret_cast<float4*>(g_query + (size_t)row * ATTD);
        for (int o4 = 4*p; o4 < 4*p + 4; o4++) {
            float v0 = (__ldg(wq_b + 4*o4+0) + dot64s(wb1 + (4*o4+0)*64, hrp)) * qs;
            float v1 = (__ldg(wq_b + 4*o4+1) + dot64s(wb1 + (4*o4+1)*64, hrp)) * qs;
            float v2 = (__ldg(wq_b + 4*o4+2) + dot64s(wb1 + (4*o4+2)*64, hrp)) * qs;
            float v3 = (__ldg(wq_b + 4*o4+3) + dot64s(wb1 + (4*o4+3)*64, hrp)) * qs;
            dst[o4] = make_float4(v0, v1, v2, v3);
        }
        __syncthreads();
    }
    {
        cload(wb1, msg_w1 + 2560, 640, tid, 256);
        float4* dst = reinterpret_cast<float4*>(g_m1h + (size_t)row * NNHD);
        for (int o4 = 4*p; o4 < 4*p + 4; o4++) {
            float v0 = __ldg(msg_b1 + 4*o4+0) + dot64s(wb0 + (4*o4+0)*80, hrp);
            float v1 = __ldg(msg_b1 + 4*o4+1) + dot64s(wb0 + (4*o4+1)*80, hrp);
            float v2 = __ldg(msg_b1 + 4*o4+2) + dot64s(wb0 + (4*o4+2)*80, hrp);
            float v3 = __ldg(msg_b1 + 4*o4+3) + dot64s(wb0 + (4*o4+3)*80, hrp);
            dst[o4] = make_float4(v0, v1, v2, v3);
        }
        __syncthreads();
    }
    {
        float4* dst = reinterpret_cast<float4*>(g_m1h + (size_t)row * NNHD) + 8;
        for (int o4 = 4*p; o4 < 4*p + 4; o4++) {
            float v0 = __ldg(msg_b1 + 32 + 4*o4+0) + dot64s(wb1 + (4*o4+0)*80, hrp);
            float v1 = __ldg(msg_b1 + 32 + 4*o4+1) + dot64s(wb1 + (4*o4+1)*80, hrp);
            float v2 = __ldg(msg_b1 + 32 + 4*o4+2) + dot64s(wb1 + (4*o4+2)*80, hrp);
            float v3 = __ldg(msg_b1 + 32 + 4*o4+3) + dot64s(wb1 + (4*o4+3)*80, hrp);
            dst[o4] = make_float4(v0, v1, v2, v3);
        }
    }
}

// ---------------- K2a/K2b: BN statistics ----------------
__global__ void __launch_bounds__(256) k2a_bn()
{
    __shared__ float ss[4][NNHD], sq[4][NNHD];
    const int tid = threadIdx.x;
    const int f = tid & 63;
    const int rg = tid >> 6;
    const int base = blockIdx.x * 256;
    float s = 0.f, q = 0.f;
    for (int r = rg; r < 256; r += 4) {
        float v = g_z1[(size_t)(base + r) * NNHD + f];
        s += v; q += v * v;
    }
    ss[rg][f] = s; sq[rg][f] = q;
    __syncthreads();
    if (tid < NNHD) {
        g_p1[blockIdx.x * NNHD + tid] = ss[0][tid] + ss[1][tid] + ss[2][tid] + ss[3][tid];
        g_p2[blockIdx.x * NNHD + tid] = sq[0][tid] + sq[1][tid] + sq[2][tid] + sq[3][tid];
    }
}
__global__ void __launch_bounds__(64) k2b_bn(const float* __restrict__ bn_g,
                                            const float* __restrict__ bn_b)
{
    const int f = threadIdx.x;
    float s = 0.f, q = 0.f;
    for (int i = 0; i < 128; i++) { s += g_p1[i * NNHD + f]; q += g_p2[i * NNHD + f]; }
    float mean = s * (1.f / (float)NROWS);
    float var  = q * (1.f / (float)NROWS) - mean * mean;
    float a = __ldg(bn_g + f) / sqrtf(var + 1e-5f);
    g_bn_a[f] = a;
    g_bn_c[f] = __ldg(bn_b + f) - a * mean;
}

// ---------------- K3m: latent GEMM via mma.sync bf16 (3-term split) ----------------
// CTA = 128 rows, 4 warps (warp w: rows w*32..w*32+31 -> batch b = blk*4+w).
// A [128x64] = lrelu(BN(z1)), bf16 hi/lo, SW128 rows in smem.
// Per chunk t (8): B [128n x 64k]: n-order = [mu d0..31 | lg d0..31 | mu d32..63 | lg d32..63],
//   lg rows prescaled by log2(e)/2. Bias folded into accumulator init.
// Epilogue on fragments: lat = mu + max(exp2(lg'), sqrt(2e-3))*eps; alpha raw scores via qk regs.
#define K3M_SA_HI 0
#define K3M_SA_LO 16384
#define K3M_SB_HI 32768
#define K3M_SB_LO 49152
#define K3M_SQK   65536
#define K3M_SQB   73728
#define K3M_SWK   74240
#define K3M_SBIAS 76288
#define K3M_SMEM  76800
#define LGSCALE 0.721347520444482f
#define SQVF    0.044721359549996f

__global__ void __launch_bounds__(128) k3m_latent(
    const float* __restrict__ eps,
    const float* __restrict__ emb_w2, const float* __restrict__ emb_b2,
    const float* __restrict__ wk_w, const float* __restrict__ wk_b)
{
    extern __shared__ char sm[];
    const uint32_t sbase = smem_u32(sm);
    float* smf = reinterpret_cast<float*>(sm);
    const int tid = threadIdx.x;
    const int w = tid >> 5;
    const int lane = tid & 31;
    const int row0 = blockIdx.x * 128;
    const int b = blockIdx.x * 4 + w;
    const int e0 = 2 * (lane & 3);

    // ---- A build: thread = row ----
    {
        const float4* zpg = reinterpret_cast<const float4*>(g_z1 + (size_t)(row0 + tid) * NNHD);
#pragma unroll
        for (int k = 0; k < 16; k++) {
            float4 v = __ldg(zpg + k);
            float t0 = g_bn_a[4*k+0] * v.x + g_bn_c[4*k+0]; t0 = t0 > 0.f ? t0 : 0.01f * t0;
            float t1 = g_bn_a[4*k+1] * v.y + g_bn_c[4*k+1]; t1 = t1 > 0.f ? t1 : 0.01f * t1;
            float t2 = g_bn_a[4*k+2] * v.z + g_bn_c[4*k+2]; t2 = t2 > 0.f ? t2 : 0.01f * t2;
            float t3 = g_bn_a[4*k+3] * v.w + g_bn_c[4*k+3]; t3 = t3 > 0.f ? t3 : 0.01f * t3;
            uint32_t h0, l0, h1, l1;
            bf_split2(t0, t1, h0, l0);
            bf_split2(t2, t3, h1, l1);
            uint32_t off = SWZ128((uint32_t)(tid * 128 + k * 8));
            *reinterpret_cast<uint2*>(sm + K3M_SA_HI + off) = make_uint2(h0, h1);
            *reinterpret_cast<uint2*>(sm + K3M_SA_LO + off) = make_uint2(l0, l1);
        }
    }
    cload(smf + K3M_SWK / 4, wk_w, 128, tid, 128);
    __syncthreads();

    // ---- qk prepass: thread = row; store to smem ----
    {
        const float* swk = smf + K3M_SWK / 4;
        float qk[16];
#pragma unroll
        for (int l = 0; l < 16; l++) qk[l] = 0.f;
        float qb = 0.f;
        const float4* qp = reinterpret_cast<const float4*>(g_query + (size_t)(row0 + tid) * ATTD);
#pragma unroll
        for (int k = 0; k < 8; k++) {
            float4 v = __ldg(qp + k);
            float qa[4] = {v.x, v.y, v.z, v.w};
#pragma unroll
            for (int u = 0; u < 4; u++) {
                int a = 4*k + u;
#pragma unroll
                for (int l = 0; l < 16; l++) qk[l] = fmaf(qa[u], swk[a*16 + l], qk[l]);
                qb = fmaf(qa[u], __ldg(wk_b + a), qb);
            }
        }
#pragma unroll
        for (int l = 0; l < 16; l++) smf[K3M_SQK / 4 + tid * 16 + l] = qk[l];
        smf[K3M_SQB / 4 + tid] = qb;
    }
    __syncthreads();

    // per-thread qk registers: 4 row-slots x 4 positions {e0, e0+1, e0+8, e0+9}
    float qkr[4][4], qbr[4];
#pragma unroll
    for (int rr = 0; rr < 4; rr++) {
        int rloc = w * 32 + ((rr >> 1) ? 16 : 0) + (lane >> 2) + ((rr & 1) ? 8 : 0);
        const float* q = smf + K3M_SQK / 4 + rloc * 16;
        qkr[rr][0] = q[e0]; qkr[rr][1] = q[e0 + 1];
        qkr[rr][2] = q[e0 + 8]; qkr[rr][3] = q[e0 + 9];
        qbr[rr] = smf[K3M_SQB / 4 + rloc];
    }

    for (int t = 0; t < 8; t++) {
        if (t > 0) __syncthreads();   // protect B smem from previous chunk's MMAs
        // ---- B build ----
#pragma unroll
        for (int k = 0; k < 16; k++) {
            int idx4 = tid + k * 128;          // 0..2047
            int n = idx4 >> 4, c4 = idx4 & 15;
            int h = n >> 6, q = (n >> 5) & 1;
            int dl = 32 * h + (n & 31);
            int wrow = (q ? 512 : 0) + 64 * t + dl;
            float sc = q ? LGSCALE : 1.f;
            float4 v = __ldg(reinterpret_cast<const float4*>(emb_w2 + wrow * 64 + c4 * 4));
            uint32_t h0, l0, h1, l1;
            bf_split2(v.x * sc, v.y * sc, h0, l0);
            bf_split2(v.z * sc, v.w * sc, h1, l1);
            uint32_t off = SWZ128((uint32_t)(n * 128 + c4 * 8));
            *reinterpret_cast<uint2*>(sm + K3M_SB_HI + off) = make_uint2(h0, h1);
            *reinterpret_cast<uint2*>(sm + K3M_SB_LO + off) = make_uint2(l0, l1);
        }
        // ---- bias (same n-order, lg prescaled) ----
        {
            int n = tid;  // 128 threads = 128 n
            int h = n >> 6, q = (n >> 5) & 1;
            int dl = 32 * h + (n & 31);
            float bv = __ldg(emb_b2 + (q ? 512 : 0) + 64 * t + dl);
            smf[K3M_SBIAS / 4 + n] = q ? bv * LGSCALE : bv;
        }
        __syncthreads();

        for (int hh = 0; hh < 2; hh++) {
            const int nbase = hh * 64;
            float acc[2][8][4];
#pragma unroll
            for (int mt = 0; mt < 2; mt++)
#pragma unroll
                for (int nt = 0; nt < 8; nt++) {
                    float b0 = smf[K3M_SBIAS / 4 + nbase + nt * 8 + e0];
                    float b1 = smf[K3M_SBIAS / 4 + nbase + nt * 8 + e0 + 1];
                    acc[mt][nt][0] = b0; acc[mt][nt][1] = b1;
                    acc[mt][nt][2] = b0; acc[mt][nt][3] = b1;
                }
#pragma unroll
            for (int kt = 0; kt < 4; kt++) {
                uint32_t ah[2][4], al[2][4];
#pragma unroll
                for (int mt = 0; mt < 2; mt++) {
                    uint32_t aoff = SWZ128((uint32_t)(
                        (w * 32 + mt * 16 + (lane & 15)) * 128 + kt * 32 + (lane >> 4) * 16));
                    ldsm_x4(ah[mt][0], ah[mt][1], ah[mt][2], ah[mt][3], sbase + K3M_SA_HI + aoff);
                    ldsm_x4(al[mt][0], al[mt][1], al[mt][2], al[mt][3], sbase + K3M_SA_LO + aoff);
                }
#pragma unroll
                for (int nt = 0; nt < 8; nt++) {
                    uint32_t boff = SWZ128((uint32_t)(
                        (nbase + nt * 8 + (lane & 7)) * 128 + kt * 32 + ((lane >> 3) & 1) * 16));
                    uint32_t bh0, bh1, bl0, bl1;
                    ldsm_x2(bh0, bh1, sbase + K3M_SB_HI + boff);
                    ldsm_x2(bl0, bl1, sbase + K3M_SB_LO + boff);
#pragma unroll
                    for (int mt = 0; mt < 2; mt++) {
                        mma16816(acc[mt][nt], ah[mt], bh0, bh1);
                        mma16816(acc[mt][nt], ah[mt], bl0, bl1);
                        mma16816(acc[mt][nt], al[mt], bh0, bh1);
                    }
                }
            }
            // ---- epilogue on fragments ----
#pragma unroll
            for (int mt = 0; mt < 2; mt++) {
#pragma unroll
                for (int h01 = 0; h01 < 2; h01++) {
                    const int rloc = w * 32 + mt * 16 + (lane >> 2) + 8 * h01;
                    const int rr = mt * 2 + h01;
                    const int i = rloc & 31;
                    float ap0 = 0.f, ap1 = 0.f;
#pragma unroll
                    for (int nt = 0; nt < 4; nt++) {
                        const int c = nt * 8 + e0;         // 0..31 within-half d index
                        float mu0 = acc[mt][nt][h01*2+0];
                        float mu1 = acc[mt][nt][h01*2+1];
                        float lg0 = acc[mt][nt+4][h01*2+0];
                        float lg1 = acc[mt][nt+4][h01*2+1];
                        float s0 = fmaxf(exp2f(lg0), SQVF);
                        float s1 = fmaxf(exp2f(lg1), SQVF);
                        const int dglob = t * 64 + 32 * hh + c;
                        float2 ev = __ldg(reinterpret_cast<const float2*>(
                            eps + (size_t)(row0 + rloc) * DLAT + dglob));
                        float l0 = fmaf(s0, ev.x, mu0);
                        float l1 = fmaf(s1, ev.y, mu1);
                        const int j = 4 * t + 2 * hh + (c >> 4);
                        const int pos = c & 15;
                        *reinterpret_cast<float2*>(
                            g_lat + (((size_t)(b * AGN + j)) * AGN + i) * LDIM + pos)
                            = make_float2(l0, l1);
                        float pa = qkr[rr][(nt & 1) * 2 + 0] * l0
                                 + qkr[rr][(nt & 1) * 2 + 1] * l1;
                        if (nt < 2) ap0 += pa; else ap1 += pa;
                    }
                    ap0 += __shfl_xor_sync(0xffffffffu, ap0, 1);
                    ap0 += __shfl_xor_sync(0xffffffffu, ap0, 2);
                    ap1 += __shfl_xor_sync(0xffffffffu, ap1, 1);
                    ap1 += __shfl_xor_sync(0xffffffffu, ap1, 2);
                    if ((lane & 3) == 0) {
                        int j0 = 4 * t + 2 * hh;
                        g_alpha[((size_t)(b * AGN + j0)) * AGN + i]     = ap0 + qbr[rr];
                        g_alpha[((size_t)(b * AGN + j0 + 1)) * AGN + i] = ap1 + qbr[rr];
                    }
                }
            }
        }
    }
}

// ---------------- K4: softmax + message MLP + weighted aggregate + q add ----------------
__global__ void __launch_bounds__(256) k4_msg(
    const float* __restrict__ msg_w1,
    const float* __restrict__ msg_w2, const float* __restrict__ msg_b2,
    float* __restrict__ ret_q)
{
    __shared__ float sW2[16 * 68];
    __shared__ float sB2[16];
    __shared__ float sU[8][68];
    __shared__ float sal[32 * 33];
    const int tid = threadIdx.x;
    const int w = tid >> 5;
    const int lane = tid & 31;
    const int b = blockIdx.x;

    for (int idx = tid; idx < 16 * 64; idx += 256) {
        int rr = idx >> 6, cc = idx & 63;
        sW2[rr * 68 + cc] = __ldg(msg_w2 + idx);
    }
    if (tid < 16) sB2[tid] = __ldg(msg_b2 + tid);
    for (int idx = tid; idx < 1024; idx += 256) {
        int jj = idx >> 5, ii = idx & 31;
        sal[jj * 33 + ii] = g_alpha[(size_t)b * 1024 + idx];
    }

    u64 w1a[8], w1b[8];
    {
        const float4* p0 = reinterpret_cast<const float4*>(msg_w1 + lane * 80 + 64);
        const float4* p1 = reinterpret_cast<const float4*>(msg_w1 + (lane + 32) * 80 + 64);
#pragma unroll
        for (int k = 0; k < 4; k++) {
            float4 v0 = __ldg(p0 + k), v1 = __ldg(p1 + k);
            w1a[2*k] = pk2(v0.x, v0.y); w1a[2*k+1] = pk2(v0.z, v0.w);
            w1b[2*k] = pk2(v1.x, v1.y); w1b[2*k+1] = pk2(v1.z, v1.w);
        }
    }
    __syncthreads();

    if (tid < 32) {
        const int ii = tid;
        float m = -3.4e38f;
#pragma unroll
        for (int j = 0; j < AGN; j++) {
            float v = (j == ii) ? -1e9f : sal[j * 33 + ii];
            m = fmaxf(m, v);
        }
        float s = 0.f;
#pragma unroll
        for (int j = 0; j < AGN; j++) {
            float v = (j == ii) ? -1e9f : sal[j * 33 + ii];
            float e = expf(v - m);
            sal[j * 33 + ii] = e;
            s += e;
        }
        float inv = 1.f / s;
#pragma unroll
        for (int j = 0; j < AGN; j++) sal[j * 33 + ii] *= inv;
    }
    __syncthreads();

#pragma unroll
    for (int jj = 0; jj < 4; jj++) {
        const int j = w + jj * 8;
        const int bj = b * AGN + j;
        const float m0 = __ldg(g_m1h + (size_t)bj * NNHD + lane);
        const float m1 = __ldg(g_m1h + (size_t)bj * NNHD + 32 + lane);
        const float* latbase = g_lat + (size_t)bj * AGN * LDIM;
        const float* alb = sal + j * 33;
        float u0 = 0.f, u1 = 0.f, sa = 0.f;

        for (int i = 0; i < AGN; i++) {
            const float4* l4 = reinterpret_cast<const float4*>(latbase + i * LDIM);
            float4 A = __ldg(l4), B = __ldg(l4+1), C = __ldg(l4+2), D = __ldg(l4+3);
            u64 z0 = pk2(A.x,A.y), z1 = pk2(A.z,A.w), z2 = pk2(B.x,B.y), z3 = pk2(B.z,B.w);
            u64 z4 = pk2(C.x,C.y), z5 = pk2(C.z,C.w), z6 = pk2(D.x,D.y), z7 = pk2(D.z,D.w);
            u64 a0 = 0ull, a1 = 0ull, b0 = 0ull, b1 = 0ull;
            a0 = fma2_(w1a[0], z0, a0); a1 = fma2_(w1a[1], z1, a1);
            b0 = fma2_(w1b[0], z0, b0); b1 = fma2_(w1b[1], z1, b1);
            a0 = fma2_(w1a[2], z2, a0); a1 = fma2_(w1a[3], z3, a1);
            b0 = fma2_(w1b[2], z2, b0); b1 = fma2_(w1b[3], z3, b1);
            a0 = fma2_(w1a[4], z4, a0); a1 = fma2_(w1a[5], z5, a1);
            b0 = fma2_(w1b[4], z4, b0); b1 = fma2_(w1b[5], z5, b1);
            a0 = fma2_(w1a[6], z6, a0); a1 = fma2_(w1a[7], z7, a1);
            b0 = fma2_(w1b[6], z6, b0); b1 = fma2_(w1b[7], z7, b1);
            float r0,r1,r2,r3; upk2(r0,r1,a0); upk2(r2,r3,a1);
            float s0 = m0 + ((r0+r1)+(r2+r3));
            upk2(r0,r1,b0); upk2(r2,r3,b1);
            float s1 = m1 + ((r0+r1)+(r2+r3));
            s0 = s0 > 0.f ? s0 : 0.01f * s0;
            s1 = s1 > 0.f ? s1 : 0.01f * s1;
            float al = alb[i];
            sa += al;
            u0 = fmaf(al, s0, u0);
            u1 = fmaf(al, s1, u1);
        }
        sU[w][lane] = u0; sU[w][32 + lane] = u1;
        __syncwarp();
        if (lane < 16) {
            float acc = __ldg(g_q + (size_t)bj * NACTD + lane) + sa * sB2[lane];
            const float* w2r = sW2 + lane * 68;
            const float* uv = sU[w];
            float c0 = 0.f, c1 = 0.f;
#pragma unroll
            for (int o = 0; o < 64; o += 2) {
                c0 = fmaf(w2r[o],   uv[o],   c0);
                c1 = fmaf(w2r[o+1], uv[o+1], c1);
            }
            ret_q[(size_t)bj * NACTD + lane] = acc + c0 + c1;
        }
        __syncwarp();
    }
}

// ---------------- host launcher ----------------
extern "C" void kernel_launch(void* const* d_in, const int* in_sizes, int n_in,
                              void* d_out, int out_size)
{
    (void)in_sizes; (void)n_in; (void)out_size;
    const float* inputs  = (const float*)d_in[0];
    const float* hidden  = (const float*)d_in[1];
    const float* eps     = (const float*)d_in[2];
    const float* fc1_w   = (const float*)d_in[3];
    const float* fc1_b   = (const float*)d_in[4];
    const float* gru_wih = (const float*)d_in[5];
    const float* gru_whh = (const float*)d_in[6];
    const float* gru_bih = (const float*)d_in[7];
    const float* gru_bhh = (const float*)d_in[8];
    const float* fc2_w   = (const float*)d_in[9];
    const float* fc2_b   = (const float*)d_in[10];
    const float* emb_w1  = (const float*)d_in[11];
    const float* emb_b1  = (const float*)d_in[12];
    const float* bn_g    = (const float*)d_in[13];
    const float* bn_b    = (const float*)d_in[14];
    const float* emb_w2  = (const float*)d_in[15];
    const float* emb_b2  = (const float*)d_in[16];
    const float* msg_w1  = (const float*)d_in[17];
    const float* msg_b1  = (const float*)d_in[18];
    const float* msg_w2  = (const float*)d_in[19];
    const float* msg_b2  = (const float*)d_in[20];
    const float* wq_w    = (const float*)d_in[21];
    const float* wq_b    = (const float*)d_in[22];
    const float* wk_w    = (const float*)d_in[23];
    const float* wk_b    = (const float*)d_in[24];

    float* out   = (float*)d_out;
    float* ret_q = out;                          // [32768,16]
    float* h_out = out + (size_t)NROWS * NACTD;  // [32768,64]

    const int K1_SMEM = (2 * 128 * XSTR + 2 * 3072) * sizeof(float);
    cudaFuncSetAttribute(k1_trunk,   cudaFuncAttributeMaxDynamicSharedMemorySize, K1_SMEM);
    cudaFuncSetAttribute(k3m_latent, cudaFuncAttributeMaxDynamicSharedMemorySize, K3M_SMEM);

    k1_trunk<<<NROWS / 128, 256, K1_SMEM>>>(
        inputs, hidden, fc1_w, fc1_b, gru_wih, gru_whh, gru_bih, gru_bhh,
        fc2_w, fc2_b, emb_w1, emb_b1, wq_w, wq_b, msg_w1, msg_b1, h_out);

    k2a_bn<<<128, 256>>>();
    k2b_bn<<<1, 64>>>(bn_g, bn_b);

    k3m_latent<<<NROWS / 128, 128, K3M_SMEM>>>(eps, emb_w2, emb_b2, wk_w, wk_b);

    k4_msg<<<BSZ, 256>>>(msg_w1, msg_w2, msg_b2, ret_q);
}

// round 7
// speedup vs baseline: 4.6844x; 1.2266x over previous
#include <cuda_runtime.h>
#include <cuda_bf16.h>
#include <cstdint>

#define NROWS 32768
#define BSZ   1024
#define AGN   32
#define IND   96
#define HDIM  64
#define NNHD  64
#define ATTD  32
#define NACTD 16
#define LDIM  16
#define DLAT  512

typedef unsigned long long u64;

// ---------------- scratch (device globals) ----------------
__device__ float g_z1[NROWS * NNHD];
__device__ float g_q[NROWS * NACTD];
__device__ float g_query[NROWS * ATTD];
__device__ float g_m1h[NROWS * NNHD];
__device__ float g_lat[BSZ * AGN * AGN * LDIM];   // [b][j][i][l]
__device__ float g_alpha[BSZ * AGN * AGN];        // RAW scores [b][j][i]
__device__ float g_bn_a[NNHD];
__device__ float g_bn_c[NNHD];
__device__ float g_p1[128 * NNHD];
__device__ float g_p2[128 * NNHD];

// ---------------- packed f32x2 helpers (k4) ----------------
__device__ __forceinline__ u64 pk2(float lo, float hi) {
    u64 r; asm("mov.b64 %0, {%1, %2};" : "=l"(r) : "f"(lo), "f"(hi)); return r;
}
__device__ __forceinline__ void upk2(float& lo, float& hi, u64 v) {
    asm("mov.b64 {%0, %1}, %2;" : "=f"(lo), "=f"(hi) : "l"(v));
}
__device__ __forceinline__ u64 fma2_(u64 a, u64 b, u64 c) {
    u64 d; asm("fma.rn.f32x2 %0, %1, %2, %3;" : "=l"(d) : "l"(a), "l"(b), "l"(c)); return d;
}
__device__ __forceinline__ void cload(float* dst, const float* __restrict__ src,
                                      int n4, int tid, int nthr) {
    float4* d = reinterpret_cast<float4*>(dst);
    const float4* s = reinterpret_cast<const float4*>(src);
    for (int i = tid; i < n4; i += nthr) d[i] = __ldg(s + i);
}
__device__ __forceinline__ float sigmoidf_(float x) {
    return __fdividef(1.f, 1.f + __expf(-x));
}

// ---------------- warp MMA plumbing ----------------
__device__ __forceinline__ uint32_t smem_u32(const void* p) {
    uint32_t a;
    asm("{ .reg .u64 t; cvta.to.shared.u64 t, %1; cvt.u32.u64 %0, t; }" : "=r"(a) : "l"(p));
    return a;
}
#define SWZ128(o) ((o) ^ (((o) >> 3) & 0x70))
__device__ __forceinline__ void ldsm_x4(uint32_t& r0, uint32_t& r1, uint32_t& r2, uint32_t& r3,
                                        uint32_t addr) {
    asm volatile("ldmatrix.sync.aligned.m8n8.x4.shared.b16 {%0,%1,%2,%3}, [%4];"
                 : "=r"(r0), "=r"(r1), "=r"(r2), "=r"(r3) : "r"(addr));
}
__device__ __forceinline__ void ldsm_x2(uint32_t& r0, uint32_t& r1, uint32_t addr) {
    asm volatile("ldmatrix.sync.aligned.m8n8.x2.shared.b16 {%0,%1}, [%2];"
                 : "=r"(r0), "=r"(r1) : "r"(addr));
}
__device__ __forceinline__ void mma16816(float* d, const uint32_t* a, uint32_t b0, uint32_t b1) {
    asm volatile(
        "mma.sync.aligned.m16n8k16.row.col.f32.bf16.bf16.f32 "
        "{%0,%1,%2,%3}, {%4,%5,%6,%7}, {%8,%9}, {%0,%1,%2,%3};"
        : "+f"(d[0]), "+f"(d[1]), "+f"(d[2]), "+f"(d[3])
        : "r"(a[0]), "r"(a[1]), "r"(a[2]), "r"(a[3]), "r"(b0), "r"(b1));
}
__device__ __forceinline__ void bf_split2(float a, float b, uint32_t& hi, uint32_t& lo) {
    __nv_bfloat16 ha = __float2bfloat16(a), hb = __float2bfloat16(b);
    float ra = a - __bfloat162float(ha);
    float rb = b - __bfloat162float(hb);
    __nv_bfloat162 H = __halves2bfloat162(ha, hb);
    __nv_bfloat162 L = __floats2bfloat162_rn(ra, rb);
    hi = *reinterpret_cast<uint32_t*>(&H);
    lo = *reinterpret_cast<uint32_t*>(&L);
}

// generic GEMM pass: acc += A(split) @ B(split)^T over NKT k-chunks, NTS n-tiles
template<int NKT, int NTS>
__device__ __forceinline__ void mma_pass(float (&acc)[2][8][4],
    uint32_t aH, uint32_t aL, uint32_t bH, uint32_t bL, int w, int lane)
{
#pragma unroll
    for (int kt = 0; kt < NKT; kt++) {
        uint32_t ah[2][4], al[2][4];
#pragma unroll
        for (int mt = 0; mt < 2; mt++) {
            uint32_t aoff = SWZ128((uint32_t)(
                (w * 32 + mt * 16 + (lane & 15)) * 128 + kt * 32 + (lane >> 4) * 16));
            ldsm_x4(ah[mt][0], ah[mt][1], ah[mt][2], ah[mt][3], aH + aoff);
            ldsm_x4(al[mt][0], al[mt][1], al[mt][2], al[mt][3], aL + aoff);
        }
#pragma unroll
        for (int nt = 0; nt < NTS; nt++) {
            uint32_t boff = SWZ128((uint32_t)(
                (nt * 8 + (lane & 7)) * 128 + kt * 32 + ((lane >> 3) & 1) * 16));
            uint32_t bh0, bh1, bl0, bl1;
            ldsm_x2(bh0, bh1, bH + boff);
            ldsm_x2(bl0, bl1, bL + boff);
#pragma unroll
            for (int mt = 0; mt < 2; mt++) {
                mma16816(acc[mt][nt], ah[mt], bh0, bh1);
                mma16816(acc[mt][nt], ah[mt], bl0, bl1);
                mma16816(acc[mt][nt], al[mt], bh0, bh1);
            }
        }
    }
}

// build [64 n x 64 k] bf16 hi/lo SW128 B tile from row-major gmem
__device__ __forceinline__ void build_b64(char* hi, char* lo,
    const float* __restrict__ src, int stride, int tid)
{
#pragma unroll
    for (int k = 0; k < 8; k++) {
        int idx4 = tid + k * 128;
        int n = idx4 >> 4, c4 = idx4 & 15;
        float4 v = __ldg(reinterpret_cast<const float4*>(src + (size_t)n * stride + c4 * 4));
        uint32_t h0, l0, h1, l1;
        bf_split2(v.x, v.y, h0, l0);
        bf_split2(v.z, v.w, h1, l1);
        uint32_t off = SWZ128((uint32_t)(n * 128 + c4 * 8));
        *reinterpret_cast<uint2*>(hi + off) = make_uint2(h0, h1);
        *reinterpret_cast<uint2*>(lo + off) = make_uint2(l0, l1);
    }
}

__device__ __forceinline__ void init_acc(float (&acc)[2][8][4], const float* sBias, int e0)
{
#pragma unroll
    for (int mt = 0; mt < 2; mt++)
#pragma unroll
        for (int nt = 0; nt < 8; nt++) {
            float b0 = sBias[nt * 8 + e0], b1 = sBias[nt * 8 + e0 + 1];
            acc[mt][nt][0] = b0; acc[mt][nt][1] = b1;
            acc[mt][nt][2] = b0; acc[mt][nt][3] = b1;
        }
}

// ---------------- K1T: trunk on tensor cores ----------------
// smem layout (bytes)
#define K1_XA_HI 0         // x_in cols 0..63 -> x (post-relu) tile
#define K1_XA_LO 16384
#define K1_XB_HI 32768     // x_in cols 64..95 (k bytes 0..63 used)
#define K1_XB_LO 49152
#define K1_H_HI  65536     // h0 -> h_new tile
#define K1_H_LO  81920
#define K1_B0_HI 98304     // B slot0 (64x64)
#define K1_B0_LO 106496
#define K1_B1_HI 114688    // B slot1
#define K1_B1_LO 122880
#define K1_SR    131072    // fp32 [128 x 66]
#define K1_SZ    164864
#define K1_SBIAS 198656    // 128 floats
#define K1_SMEM  199168

__global__ void __launch_bounds__(128) k1t_trunk(
    const float* __restrict__ inp, const float* __restrict__ h0in,
    const float* __restrict__ fc1_w, const float* __restrict__ fc1_b,
    const float* __restrict__ wih, const float* __restrict__ whh,
    const float* __restrict__ bih, const float* __restrict__ bhh,
    const float* __restrict__ fc2_w, const float* __restrict__ fc2_b,
    const float* __restrict__ emb_w1, const float* __restrict__ emb_b1,
    const float* __restrict__ wq_w, const float* __restrict__ wq_b,
    const float* __restrict__ msg_w1, const float* __restrict__ msg_b1,
    float* __restrict__ h_out)
{
    extern __shared__ char sm[];
    const uint32_t sbase = smem_u32(sm);
    float* smf = reinterpret_cast<float*>(sm);
    float* sBias = smf + K1_SBIAS / 4;
    const int tid = threadIdx.x;
    const int w = tid >> 5;
    const int lane = tid & 31;
    const int e0 = 2 * (lane & 3);
    const int row0 = blockIdx.x * 128;
    const float qs = 0.17677669529663687f;

    // ---- A build: thread = row ----
    {
        const float4* ip = reinterpret_cast<const float4*>(inp + (size_t)(row0 + tid) * IND);
#pragma unroll
        for (int k = 0; k < 24; k++) {
            float4 v = __ldg(ip + k);
            uint32_t hA, lA, hB, lB;
            bf_split2(v.x, v.y, hA, lA);
            bf_split2(v.z, v.w, hB, lB);
            if (k < 16) {
                uint32_t off = SWZ128((uint32_t)(tid * 128 + k * 8));
                *reinterpret_cast<uint2*>(sm + K1_XA_HI + off) = make_uint2(hA, hB);
                *reinterpret_cast<uint2*>(sm + K1_XA_LO + off) = make_uint2(lA, lB);
            } else {
                uint32_t off = SWZ128((uint32_t)(tid * 128 + (k - 16) * 8));
                *reinterpret_cast<uint2*>(sm + K1_XB_HI + off) = make_uint2(hA, hB);
                *reinterpret_cast<uint2*>(sm + K1_XB_LO + off) = make_uint2(lA, lB);
            }
        }
        const float4* hp = reinterpret_cast<const float4*>(h0in + (size_t)(row0 + tid) * HDIM);
#pragma unroll
        for (int k = 0; k < 16; k++) {
            float4 v = __ldg(hp + k);
            uint32_t hA, lA, hB, lB;
            bf_split2(v.x, v.y, hA, lA);
            bf_split2(v.z, v.w, hB, lB);
            uint32_t off = SWZ128((uint32_t)(tid * 128 + k * 8));
            *reinterpret_cast<uint2*>(sm + K1_H_HI + off) = make_uint2(hA, hB);
            *reinterpret_cast<uint2*>(sm + K1_H_LO + off) = make_uint2(lA, lB);
        }
    }
    // ---- fc1 B: slot0 = cols 0..63, slot1 = cols 64..95 ----
    build_b64(sm + K1_B0_HI, sm + K1_B0_LO, fc1_w, IND, tid);
#pragma unroll
    for (int k = 0; k < 4; k++) {
        int idx = tid + k * 128;      // 0..511
        int n = idx >> 3, c4 = idx & 7;
        float4 v = __ldg(reinterpret_cast<const float4*>(fc1_w + (size_t)n * IND + 64 + c4 * 4));
        uint32_t h0_, l0_, h1_, l1_;
        bf_split2(v.x, v.y, h0_, l0_);
        bf_split2(v.z, v.w, h1_, l1_);
        uint32_t off = SWZ128((uint32_t)(n * 128 + c4 * 8));
        *reinterpret_cast<uint2*>(sm + K1_B1_HI + off) = make_uint2(h0_, h1_);
        *reinterpret_cast<uint2*>(sm + K1_B1_LO + off) = make_uint2(l0_, l1_);
    }
    if (tid < 64) sBias[tid] = __ldg(fc1_b + tid);
    __syncthreads();

    float acc[2][8][4];

    // ---- fc1 GEMM + relu -> x tile (XA region) ----
    init_acc(acc, sBias, e0);
    mma_pass<4, 8>(acc, sbase + K1_XA_HI, sbase + K1_XA_LO, sbase + K1_B0_HI, sbase + K1_B0_LO, w, lane);
    mma_pass<2, 8>(acc, sbase + K1_XB_HI, sbase + K1_XB_LO, sbase + K1_B1_HI, sbase + K1_B1_LO, w, lane);
#pragma unroll
    for (int mt = 0; mt < 2; mt++)
#pragma unroll
        for (int h01 = 0; h01 < 2; h01++) {
            int row = w * 32 + mt * 16 + (lane >> 2) + 8 * h01;
#pragma unroll
            for (int nt = 0; nt < 8; nt++) {
                int c = nt * 8 + e0;
                float v0 = fmaxf(acc[mt][nt][h01 * 2 + 0], 0.f);
                float v1 = fmaxf(acc[mt][nt][h01 * 2 + 1], 0.f);
                uint32_t hh, ll;
                bf_split2(v0, v1, hh, ll);
                uint32_t off = SWZ128((uint32_t)(row * 128 + c * 2));
                *reinterpret_cast<uint32_t*>(sm + K1_XA_HI + off) = hh;
                *reinterpret_cast<uint32_t*>(sm + K1_XA_LO + off) = ll;
            }
        }
    __syncthreads();

    // ---- GRU r gate ----
    build_b64(sm + K1_B0_HI, sm + K1_B0_LO, wih, HDIM, tid);
    build_b64(sm + K1_B1_HI, sm + K1_B1_LO, whh, HDIM, tid);
    if (tid < 64) sBias[tid] = __ldg(bih + tid) + __ldg(bhh + tid);
    __syncthreads();
    init_acc(acc, sBias, e0);
    mma_pass<4, 8>(acc, sbase + K1_XA_HI, sbase + K1_XA_LO, sbase + K1_B0_HI, sbase + K1_B0_LO, w, lane);
    mma_pass<4, 8>(acc, sbase + K1_H_HI,  sbase + K1_H_LO,  sbase + K1_B1_HI, sbase + K1_B1_LO, w, lane);
#pragma unroll
    for (int mt = 0; mt < 2; mt++)
#pragma unroll
        for (int h01 = 0; h01 < 2; h01++) {
            int row = w * 32 + mt * 16 + (lane >> 2) + 8 * h01;
#pragma unroll
            for (int nt = 0; nt < 8; nt++) {
                int c = nt * 8 + e0;
                *reinterpret_cast<float2*>(smf + K1_SR / 4 + row * 66 + c) =
                    make_float2(sigmoidf_(acc[mt][nt][h01 * 2 + 0]),
                                sigmoidf_(acc[mt][nt][h01 * 2 + 1]));
            }
        }
    __syncthreads();

    // ---- GRU z gate ----
    build_b64(sm + K1_B0_HI, sm + K1_B0_LO, wih + 64 * HDIM, HDIM, tid);
    build_b64(sm + K1_B1_HI, sm + K1_B1_LO, whh + 64 * HDIM, HDIM, tid);
    if (tid < 64) sBias[tid] = __ldg(bih + 64 + tid) + __ldg(bhh + 64 + tid);
    __syncthreads();
    init_acc(acc, sBias, e0);
    mma_pass<4, 8>(acc, sbase + K1_XA_HI, sbase + K1_XA_LO, sbase + K1_B0_HI, sbase + K1_B0_LO, w, lane);
    mma_pass<4, 8>(acc, sbase + K1_H_HI,  sbase + K1_H_LO,  sbase + K1_B1_HI, sbase + K1_B1_LO, w, lane);
#pragma unroll
    for (int mt = 0; mt < 2; mt++)
#pragma unroll
        for (int h01 = 0; h01 < 2; h01++) {
            int row = w * 32 + mt * 16 + (lane >> 2) + 8 * h01;
#pragma unroll
            for (int nt = 0; nt < 8; nt++) {
                int c = nt * 8 + e0;
                *reinterpret_cast<float2*>(smf + K1_SZ / 4 + row * 66 + c) =
                    make_float2(sigmoidf_(acc[mt][nt][h01 * 2 + 0]),
                                sigmoidf_(acc[mt][nt][h01 * 2 + 1]));
            }
        }
    __syncthreads();

    // ---- GRU n gate: gi_n (x) and gh_n (h) kept in regs ----
    build_b64(sm + K1_B0_HI, sm + K1_B0_LO, wih + 128 * HDIM, HDIM, tid);
    build_b64(sm + K1_B1_HI, sm + K1_B1_LO, whh + 128 * HDIM, HDIM, tid);
    if (tid < 64) sBias[tid] = __ldg(bih + 128 + tid);
    else sBias[tid] = __ldg(bhh + 128 + (tid - 64));
    __syncthreads();
    float acc2[2][8][4];
    init_acc(acc, sBias, e0);
    init_acc(acc2, sBias + 64, e0);
    mma_pass<4, 8>(acc,  sbase + K1_XA_HI, sbase + K1_XA_LO, sbase + K1_B0_HI, sbase + K1_B0_LO, w, lane);
    mma_pass<4, 8>(acc2, sbase + K1_H_HI,  sbase + K1_H_LO,  sbase + K1_B1_HI, sbase + K1_B1_LO, w, lane);

    // ---- blend: h = (1-z)*tanh(gin + r*ghn) + z*h0 ----
#pragma unroll
    for (int mt = 0; mt < 2; mt++)
#pragma unroll
        for (int h01 = 0; h01 < 2; h01++) {
            int row = w * 32 + mt * 16 + (lane >> 2) + 8 * h01;
            int grow = row0 + row;
#pragma unroll
            for (int nt = 0; nt < 8; nt++) {
                int c = nt * 8 + e0;
                float2 rv = *reinterpret_cast<const float2*>(smf + K1_SR / 4 + row * 66 + c);
                float2 zv = *reinterpret_cast<const float2*>(smf + K1_SZ / 4 + row * 66 + c);
                float n0 = tanhf(acc[mt][nt][h01 * 2 + 0] + rv.x * acc2[mt][nt][h01 * 2 + 0]);
                float n1 = tanhf(acc[mt][nt][h01 * 2 + 1] + rv.y * acc2[mt][nt][h01 * 2 + 1]);
                float2 h0v = __ldg(reinterpret_cast<const float2*>(h0in + (size_t)grow * HDIM + c));
                float hn0 = (1.f - zv.x) * n0 + zv.x * h0v.x;
                float hn1 = (1.f - zv.y) * n1 + zv.y * h0v.y;
                *reinterpret_cast<float2*>(h_out + (size_t)grow * HDIM + c) = make_float2(hn0, hn1);
                uint32_t hh, ll;
                bf_split2(hn0, hn1, hh, ll);
                uint32_t off = SWZ128((uint32_t)(row * 128 + c * 2));
                *reinterpret_cast<uint32_t*>(sm + K1_H_HI + off) = hh;
                *reinterpret_cast<uint32_t*>(sm + K1_H_LO + off) = ll;
            }
        }
    __syncthreads();

    // ---- heads: rows 0..175 = fc2(16) | emb_w1(64) | wq*qs(32) | msg_w1[:, :64](64) ----
#pragma unroll
    for (int p = 0; p < 3; p++) {
        const int rows = (p == 2) ? 48 : 64;
        // build B slot0
#pragma unroll
        for (int k = 0; k < 8; k++) {
            int idx4 = tid + k * 128;
            int n = idx4 >> 4, c4 = idx4 & 15;
            if (n < rows) {
                int g = p * 64 + n;
                const float* src; float sc = 1.f;
                if (g < 16)       src = fc2_w + (size_t)g * HDIM;
                else if (g < 80)  src = emb_w1 + (size_t)(g - 16) * HDIM;
                else if (g < 112) { src = wq_w + (size_t)(g - 80) * HDIM; sc = qs; }
                else              src = msg_w1 + (size_t)(g - 112) * 80;
                float4 v = __ldg(reinterpret_cast<const float4*>(src + c4 * 4));
                uint32_t h0_, l0_, h1_, l1_;
                bf_split2(v.x * sc, v.y * sc, h0_, l0_);
                bf_split2(v.z * sc, v.w * sc, h1_, l1_);
                uint32_t off = SWZ128((uint32_t)(n * 128 + c4 * 8));
                *reinterpret_cast<uint2*>(sm + K1_B0_HI + off) = make_uint2(h0_, h1_);
                *reinterpret_cast<uint2*>(sm + K1_B0_LO + off) = make_uint2(l0_, l1_);
            }
        }
        if (tid < rows) {
            int g = p * 64 + tid; float bv;
            if (g < 16)       bv = __ldg(fc2_b + g);
            else if (g < 80)  bv = __ldg(emb_b1 + g - 16);
            else if (g < 112) bv = __ldg(wq_b + g - 80) * qs;
            else              bv = __ldg(msg_b1 + g - 112);
            sBias[tid] = bv;
        }
        __syncthreads();
        init_acc(acc, sBias, e0);
        if (p == 2)
            mma_pass<4, 6>(acc, sbase + K1_H_HI, sbase + K1_H_LO, sbase + K1_B0_HI, sbase + K1_B0_LO, w, lane);
        else
            mma_pass<4, 8>(acc, sbase + K1_H_HI, sbase + K1_H_LO, sbase + K1_B0_HI, sbase + K1_B0_LO, w, lane);
        const int nts = (p == 2) ? 6 : 8;
#pragma unroll
        for (int mt = 0; mt < 2; mt++)
#pragma unroll
            for (int h01 = 0; h01 < 2; h01++) {
                int row = w * 32 + mt * 16 + (lane >> 2) + 8 * h01;
                int grow = row0 + row;
                for (int nt = 0; nt < nts; nt++) {
                    int cg = p * 64 + nt * 8 + e0;
                    float v0 = acc[mt][nt][h01 * 2 + 0];
                    float v1 = acc[mt][nt][h01 * 2 + 1];
                    float* dst;
                    if (cg < 16)       dst = g_q + (size_t)grow * NACTD + cg;
                    else if (cg < 80)  dst = g_z1 + (size_t)grow * NNHD + (cg - 16);
                    else if (cg < 112) dst = g_query + (size_t)grow * ATTD + (cg - 80);
                    else               dst = g_m1h + (size_t)grow * NNHD + (cg - 112);
                    *reinterpret_cast<float2*>(dst) = make_float2(v0, v1);
                }
            }
        __syncthreads();
    }
}

// ---------------- K2a/K2b: BN statistics ----------------
__global__ void __launch_bounds__(256) k2a_bn()
{
    __shared__ float ss[4][NNHD], sq[4][NNHD];
    const int tid = threadIdx.x;
    const int f = tid & 63;
    const int rg = tid >> 6;
    const int base = blockIdx.x * 256;
    float s = 0.f, q = 0.f;
    for (int r = rg; r < 256; r += 4) {
        float v = g_z1[(size_t)(base + r) * NNHD + f];
        s += v; q += v * v;
    }
    ss[rg][f] = s; sq[rg][f] = q;
    __syncthreads();
    if (tid < NNHD) {
        g_p1[blockIdx.x * NNHD + tid] = ss[0][tid] + ss[1][tid] + ss[2][tid] + ss[3][tid];
        g_p2[blockIdx.x * NNHD + tid] = sq[0][tid] + sq[1][tid] + sq[2][tid] + sq[3][tid];
    }
}
__global__ void __launch_bounds__(64) k2b_bn(const float* __restrict__ bn_g,
                                            const float* __restrict__ bn_b)
{
    const int f = threadIdx.x;
    float s = 0.f, q = 0.f;
    for (int i = 0; i < 128; i++) { s += g_p1[i * NNHD + f]; q += g_p2[i * NNHD + f]; }
    float mean = s * (1.f / (float)NROWS);
    float var  = q * (1.f / (float)NROWS) - mean * mean;
    float a = __ldg(bn_g + f) / sqrtf(var + 1e-5f);
    g_bn_a[f] = a;
    g_bn_c[f] = __ldg(bn_b + f) - a * mean;
}

// ---------------- K3m: latent GEMM via mma.sync bf16 (unchanged, R6) ----------------
#define K3M_SA_HI 0
#define K3M_SA_LO 16384
#define K3M_SB_HI 32768
#define K3M_SB_LO 49152
#define K3M_SQK   65536
#define K3M_SQB   73728
#define K3M_SWK   74240
#define K3M_SBIAS 76288
#define K3M_SMEM  76800
#define LGSCALE 0.721347520444482f
#define SQVF    0.044721359549996f

__global__ void __launch_bounds__(128) k3m_latent(
    const float* __restrict__ eps,
    const float* __restrict__ emb_w2, const float* __restrict__ emb_b2,
    const float* __restrict__ wk_w, const float* __restrict__ wk_b)
{
    extern __shared__ char sm[];
    const uint32_t sbase = smem_u32(sm);
    float* smf = reinterpret_cast<float*>(sm);
    const int tid = threadIdx.x;
    const int w = tid >> 5;
    const int lane = tid & 31;
    const int row0 = blockIdx.x * 128;
    const int b = blockIdx.x * 4 + w;
    const int e0 = 2 * (lane & 3);

    {
        const float4* zpg = reinterpret_cast<const float4*>(g_z1 + (size_t)(row0 + tid) * NNHD);
#pragma unroll
        for (int k = 0; k < 16; k++) {
            float4 v = __ldg(zpg + k);
            float t0 = g_bn_a[4*k+0] * v.x + g_bn_c[4*k+0]; t0 = t0 > 0.f ? t0 : 0.01f * t0;
            float t1 = g_bn_a[4*k+1] * v.y + g_bn_c[4*k+1]; t1 = t1 > 0.f ? t1 : 0.01f * t1;
            float t2 = g_bn_a[4*k+2] * v.z + g_bn_c[4*k+2]; t2 = t2 > 0.f ? t2 : 0.01f * t2;
            float t3 = g_bn_a[4*k+3] * v.w + g_bn_c[4*k+3]; t3 = t3 > 0.f ? t3 : 0.01f * t3;
            uint32_t h0, l0, h1, l1;
            bf_split2(t0, t1, h0, l0);
            bf_split2(t2, t3, h1, l1);
            uint32_t off = SWZ128((uint32_t)(tid * 128 + k * 8));
            *reinterpret_cast<uint2*>(sm + K3M_SA_HI + off) = make_uint2(h0, h1);
            *reinterpret_cast<uint2*>(sm + K3M_SA_LO + off) = make_uint2(l0, l1);
        }
    }
    cload(smf + K3M_SWK / 4, wk_w, 128, tid, 128);
    __syncthreads();

    {
        const float* swk = smf + K3M_SWK / 4;
        float qk[16];
#pragma unroll
        for (int l = 0; l < 16; l++) qk[l] = 0.f;
        float qb = 0.f;
        const float4* qp = reinterpret_cast<const float4*>(g_query + (size_t)(row0 + tid) * ATTD);
#pragma unroll
        for (int k = 0; k < 8; k++) {
            float4 v = __ldg(qp + k);
            float qa[4] = {v.x, v.y, v.z, v.w};
#pragma unroll
            for (int u = 0; u < 4; u++) {
                int a = 4*k + u;
#pragma unroll
                for (int l = 0; l < 16; l++) qk[l] = fmaf(qa[u], swk[a*16 + l], qk[l]);
                qb = fmaf(qa[u], __ldg(wk_b + a), qb);
            }
        }
#pragma unroll
        for (int l = 0; l < 16; l++) smf[K3M_SQK / 4 + tid * 16 + l] = qk[l];
        smf[K3M_SQB / 4 + tid] = qb;
    }
    __syncthreads();

    float qkr[4][4], qbr[4];
#pragma unroll
    for (int rr = 0; rr < 4; rr++) {
        int rloc = w * 32 + ((rr >> 1) ? 16 : 0) + (lane >> 2) + ((rr & 1) ? 8 : 0);
        const float* q = smf + K3M_SQK / 4 + rloc * 16;
        qkr[rr][0] = q[e0]; qkr[rr][1] = q[e0 + 1];
        qkr[rr][2] = q[e0 + 8]; qkr[rr][3] = q[e0 + 9];
        qbr[rr] = smf[K3M_SQB / 4 + rloc];
    }

    for (int t = 0; t < 8; t++) {
        if (t > 0) __syncthreads();
#pragma unroll
        for (int k = 0; k < 16; k++) {
            int idx4 = tid + k * 128;
            int n = idx4 >> 4, c4 = idx4 & 15;
            int h = n >> 6, q = (n >> 5) & 1;
            int dl = 32 * h + (n & 31);
            int wrow = (q ? 512 : 0) + 64 * t + dl;
            float sc = q ? LGSCALE : 1.f;
            float4 v = __ldg(reinterpret_cast<const float4*>(emb_w2 + wrow * 64 + c4 * 4));
            uint32_t h0, l0, h1, l1;
            bf_split2(v.x * sc, v.y * sc, h0, l0);
            bf_split2(v.z * sc, v.w * sc, h1, l1);
            uint32_t off = SWZ128((uint32_t)(n * 128 + c4 * 8));
            *reinterpret_cast<uint2*>(sm + K3M_SB_HI + off) = make_uint2(h0, h1);
            *reinterpret_cast<uint2*>(sm + K3M_SB_LO + off) = make_uint2(l0, l1);
        }
        {
            int n = tid;
            int h = n >> 6, q = (n >> 5) & 1;
            int dl = 32 * h + (n & 31);
            float bv = __ldg(emb_b2 + (q ? 512 : 0) + 64 * t + dl);
            smf[K3M_SBIAS / 4 + n] = q ? bv * LGSCALE : bv;
        }
        __syncthreads();

        for (int hh = 0; hh < 2; hh++) {
            const int nbase = hh * 64;
            float acc[2][8][4];
#pragma unroll
            for (int mt = 0; mt < 2; mt++)
#pragma unroll
                for (int nt = 0; nt < 8; nt++) {
                    float b0 = smf[K3M_SBIAS / 4 + nbase + nt * 8 + e0];
                    float b1 = smf[K3M_SBIAS / 4 + nbase + nt * 8 + e0 + 1];
                    acc[mt][nt][0] = b0; acc[mt][nt][1] = b1;
                    acc[mt][nt][2] = b0; acc[mt][nt][3] = b1;
                }
#pragma unroll
            for (int kt = 0; kt < 4; kt++) {
                uint32_t ah[2][4], al[2][4];
#pragma unroll
                for (int mt = 0; mt < 2; mt++) {
                    uint32_t aoff = SWZ128((uint32_t)(
                        (w * 32 + mt * 16 + (lane & 15)) * 128 + kt * 32 + (lane >> 4) * 16));
                    ldsm_x4(ah[mt][0], ah[mt][1], ah[mt][2], ah[mt][3], sbase + K3M_SA_HI + aoff);
                    ldsm_x4(al[mt][0], al[mt][1], al[mt][2], al[mt][3], sbase + K3M_SA_LO + aoff);
                }
#pragma unroll
                for (int nt = 0; nt < 8; nt++) {
                    uint32_t boff = SWZ128((uint32_t)(
                        (nbase + nt * 8 + (lane & 7)) * 128 + kt * 32 + ((lane >> 3) & 1) * 16));
                    uint32_t bh0, bh1, bl0, bl1;
                    ldsm_x2(bh0, bh1, sbase + K3M_SB_HI + boff);
                    ldsm_x2(bl0, bl1, sbase + K3M_SB_LO + boff);
#pragma unroll
                    for (int mt = 0; mt < 2; mt++) {
                        mma16816(acc[mt][nt], ah[mt], bh0, bh1);
                        mma16816(acc[mt][nt], ah[mt], bl0, bl1);
                        mma16816(acc[mt][nt], al[mt], bh0, bh1);
                    }
                }
            }
#pragma unroll
            for (int mt = 0; mt < 2; mt++) {
#pragma unroll
                for (int h01 = 0; h01 < 2; h01++) {
                    const int rloc = w * 32 + mt * 16 + (lane >> 2) + 8 * h01;
                    const int rr = mt * 2 + h01;
                    const int i = rloc & 31;
                    float ap0 = 0.f, ap1 = 0.f;
#pragma unroll
                    for (int nt = 0; nt < 4; nt++) {
                        const int c = nt * 8 + e0;
                        float mu0 = acc[mt][nt][h01*2+0];
                        float mu1 = acc[mt][nt][h01*2+1];
                        float lg0 = acc[mt][nt+4][h01*2+0];
                        float lg1 = acc[mt][nt+4][h01*2+1];
                        float s0 = fmaxf(exp2f(lg0), SQVF);
                        float s1 = fmaxf(exp2f(lg1), SQVF);
                        const int dglob = t * 64 + 32 * hh + c;
                        float2 ev = __ldg(reinterpret_cast<const float2*>(
                            eps + (size_t)(row0 + rloc) * DLAT + dglob));
                        float l0 = fmaf(s0, ev.x, mu0);
                        float l1 = fmaf(s1, ev.y, mu1);
                        const int j = 4 * t + 2 * hh + (c >> 4);
                        const int pos = c & 15;
                        *reinterpret_cast<float2*>(
                            g_lat + (((size_t)(b * AGN + j)) * AGN + i) * LDIM + pos)
                            = make_float2(l0, l1);
                        float pa = qkr[rr][(nt & 1) * 2 + 0] * l0
                                 + qkr[rr][(nt & 1) * 2 + 1] * l1;
                        if (nt < 2) ap0 += pa; else ap1 += pa;
                    }
                    ap0 += __shfl_xor_sync(0xffffffffu, ap0, 1);
                    ap0 += __shfl_xor_sync(0xffffffffu, ap0, 2);
                    ap1 += __shfl_xor_sync(0xffffffffu, ap1, 1);
                    ap1 += __shfl_xor_sync(0xffffffffu, ap1, 2);
                    if ((lane & 3) == 0) {
                        int j0 = 4 * t + 2 * hh;
                        g_alpha[((size_t)(b * AGN + j0)) * AGN + i]     = ap0 + qbr[rr];
                        g_alpha[((size_t)(b * AGN + j0 + 1)) * AGN + i] = ap1 + qbr[rr];
                    }
                }
            }
        }
    }
}

// ---------------- K4: softmax + message MLP + aggregate (unchanged, R6) ----------------
__global__ void __launch_bounds__(256) k4_msg(
    const float* __restrict__ msg_w1,
    const float* __restrict__ msg_w2, const float* __restrict__ msg_b2,
    float* __restrict__ ret_q)
{
    __shared__ float sW2[16 * 68];
    __shared__ float sB2[16];
    __shared__ float sU[8][68];
    __shared__ float sal[32 * 33];
    const int tid = threadIdx.x;
    const int w = tid >> 5;
    const int lane = tid & 31;
    const int b = blockIdx.x;

    for (int idx = tid; idx < 16 * 64; idx += 256) {
        int rr = idx >> 6, cc = idx & 63;
        sW2[rr * 68 + cc] = __ldg(msg_w2 + idx);
    }
    if (tid < 16) sB2[tid] = __ldg(msg_b2 + tid);
    for (int idx = tid; idx < 1024; idx += 256) {
        int jj = idx >> 5, ii = idx & 31;
        sal[jj * 33 + ii] = g_alpha[(size_t)b * 1024 + idx];
    }

    u64 w1a[8], w1b[8];
    {
        const float4* p0 = reinterpret_cast<const float4*>(msg_w1 + lane * 80 + 64);
        const float4* p1 = reinterpret_cast<const float4*>(msg_w1 + (lane + 32) * 80 + 64);
#pragma unroll
        for (int k = 0; k < 4; k++) {
            float4 v0 = __ldg(p0 + k), v1 = __ldg(p1 + k);
            w1a[2*k] = pk2(v0.x, v0.y); w1a[2*k+1] = pk2(v0.z, v0.w);
            w1b[2*k] = pk2(v1.x, v1.y); w1b[2*k+1] = pk2(v1.z, v1.w);
        }
    }
    __syncthreads();

    if (tid < 32) {
        const int ii = tid;
        float m = -3.4e38f;
#pragma unroll
        for (int j = 0; j < AGN; j++) {
            float v = (j == ii) ? -1e9f : sal[j * 33 + ii];
            m = fmaxf(m, v);
        }
        float s = 0.f;
#pragma unroll
        for (int j = 0; j < AGN; j++) {
            float v = (j == ii) ? -1e9f : sal[j * 33 + ii];
            float e = expf(v - m);
            sal[j * 33 + ii] = e;
            s += e;
        }
        float inv = 1.f / s;
#pragma unroll
        for (int j = 0; j < AGN; j++) sal[j * 33 + ii] *= inv;
    }
    __syncthreads();

#pragma unroll
    for (int jj = 0; jj < 4; jj++) {
        const int j = w + jj * 8;
        const int bj = b * AGN + j;
        const float m0 = __ldg(g_m1h + (size_t)bj * NNHD + lane);
        const float m1 = __ldg(g_m1h + (size_t)bj * NNHD + 32 + lane);
        const float* latbase = g_lat + (size_t)bj * AGN * LDIM;
        const float* alb = sal + j * 33;
        float u0 = 0.f, u1 = 0.f, sa = 0.f;

        for (int i = 0; i < AGN; i++) {
            const float4* l4 = reinterpret_cast<const float4*>(latbase + i * LDIM);
            float4 A = __ldg(l4), B = __ldg(l4+1), C = __ldg(l4+2), D = __ldg(l4+3);
            u64 z0 = pk2(A.x,A.y), z1 = pk2(A.z,A.w), z2 = pk2(B.x,B.y), z3 = pk2(B.z,B.w);
            u64 z4 = pk2(C.x,C.y), z5 = pk2(C.z,C.w), z6 = pk2(D.x,D.y), z7 = pk2(D.z,D.w);
            u64 a0 = 0ull, a1 = 0ull, b0 = 0ull, b1 = 0ull;
            a0 = fma2_(w1a[0], z0, a0); a1 = fma2_(w1a[1], z1, a1);
            b0 = fma2_(w1b[0], z0, b0); b1 = fma2_(w1b[1], z1, b1);
            a0 = fma2_(w1a[2], z2, a0); a1 = fma2_(w1a[3], z3, a1);
            b0 = fma2_(w1b[2], z2, b0); b1 = fma2_(w1b[3], z3, b1);
            a0 = fma2_(w1a[4], z4, a0); a1 = fma2_(w1a[5], z5, a1);
            b0 = fma2_(w1b[4], z4, b0); b1 = fma2_(w1b[5], z5, b1);
            a0 = fma2_(w1a[6], z6, a0); a1 = fma2_(w1a[7], z7, a1);
            b0 = fma2_(w1b[6], z6, b0); b1 = fma2_(w1b[7], z7, b1);
            float r0,r1,r2,r3; upk2(r0,r1,a0); upk2(r2,r3,a1);
            float s0 = m0 + ((r0+r1)+(r2+r3));
            upk2(r0,r1,b0); upk2(r2,r3,b1);
            float s1 = m1 + ((r0+r1)+(r2+r3));
            s0 = s0 > 0.f ? s0 : 0.01f * s0;
            s1 = s1 > 0.f ? s1 : 0.01f * s1;
            float al = alb[i];
            sa += al;
            u0 = fmaf(al, s0, u0);
            u1 = fmaf(al, s1, u1);
        }
        sU[w][lane] = u0; sU[w][32 + lane] = u1;
        __syncwarp();
        if (lane < 16) {
            float acc = __ldg(g_q + (size_t)bj * NACTD + lane) + sa * sB2[lane];
            const float* w2r = sW2 + lane * 68;
            const float* uv = sU[w];
            float c0 = 0.f, c1 = 0.f;
#pragma unroll
            for (int o = 0; o < 64; o += 2) {
                c0 = fmaf(w2r[o],   uv[o],   c0);
                c1 = fmaf(w2r[o+1], uv[o+1], c1);
            }
            ret_q[(size_t)bj * NACTD + lane] = acc + c0 + c1;
        }
        __syncwarp();
    }
}

// ---------------- host launcher ----------------
extern "C" void kernel_launch(void* const* d_in, const int* in_sizes, int n_in,
                              void* d_out, int out_size)
{
    (void)in_sizes; (void)n_in; (void)out_size;
    const float* inputs  = (const float*)d_in[0];
    const float* hidden  = (const float*)d_in[1];
    const float* eps     = (const float*)d_in[2];
    const float* fc1_w   = (const float*)d_in[3];
    const float* fc1_b   = (const float*)d_in[4];
    const float* gru_wih = (const float*)d_in[5];
    const float* gru_whh = (const float*)d_in[6];
    const float* gru_bih = (const float*)d_in[7];
    const float* gru_bhh = (const float*)d_in[8];
    const float* fc2_w   = (const float*)d_in[9];
    const float* fc2_b   = (const float*)d_in[10];
    const float* emb_w1  = (const float*)d_in[11];
    const float* emb_b1  = (const float*)d_in[12];
    const float* bn_g    = (const float*)d_in[13];
    const float* bn_b    = (const float*)d_in[14];
    const float* emb_w2  = (const float*)d_in[15];
    const float* emb_b2  = (const float*)d_in[16];
    const float* msg_w1  = (const float*)d_in[17];
    const float* msg_b1  = (const float*)d_in[18];
    const float* msg_w2  = (const float*)d_in[19];
    const float* msg_b2  = (const float*)d_in[20];
    const float* wq_w    = (const float*)d_in[21];
    const float* wq_b    = (const float*)d_in[22];
    const float* wk_w    = (const float*)d_in[23];
    const float* wk_b    = (const float*)d_in[24];

    float* out   = (float*)d_out;
    float* ret_q = out;                          // [32768,16]
    float* h_out = out + (size_t)NROWS * NACTD;  // [32768,64]

    cudaFuncSetAttribute(k1t_trunk,  cudaFuncAttributeMaxDynamicSharedMemorySize, K1_SMEM);
    cudaFuncSetAttribute(k3m_latent, cudaFuncAttributeMaxDynamicSharedMemorySize, K3M_SMEM);

    k1t_trunk<<<NROWS / 128, 128, K1_SMEM>>>(
        inputs, hidden, fc1_w, fc1_b, gru_wih, gru_whh, gru_bih, gru_bhh,
        fc2_w, fc2_b, emb_w1, emb_b1, wq_w, wq_b, msg_w1, msg_b1, h_out);

    k2a_bn<<<128, 256>>>();
    k2b_bn<<<1, 64>>>(bn_g, bn_b);

    k3m_latent<<<NROWS / 128, 128, K3M_SMEM>>>(eps, emb_w2, emb_b2, wk_w, wk_b);

    k4_msg<<<BSZ, 256>>>(msg_w1, msg_w2, msg_b2, ret_q);
}